// round 12
// baseline (speedup 1.0000x reference)
#include <cuda_runtime.h>
#include <cuda_bf16.h>
#include <float.h>
#include <math.h>
#include <stdint.h>

#define S_LEN 2048
#define EMB   1024
#define NH    16
#define HD    64
#define NB    2
#define NTOK  (NB * S_LEN)   // 4096

// ---------------- scratch (device globals: no allocation allowed) ------------
__device__ float g_linv[(size_t)NB * NH * S_LEN];     // per-row 1/l

__device__ __nv_bfloat16 g_qh[(size_t)NB * NH * S_LEN * HD];  // [B,H,S,D]
__device__ __nv_bfloat16 g_ql[(size_t)NB * NH * S_LEN * HD];
__device__ __nv_bfloat16 g_kh[(size_t)NB * NH * S_LEN * HD];
__device__ __nv_bfloat16 g_kl[(size_t)NB * NH * S_LEN * HD];
__device__ __nv_bfloat16 g_vh[(size_t)NB * NH * S_LEN * HD];
__device__ __nv_bfloat16 g_vl[(size_t)NB * NH * S_LEN * HD];
__device__ __nv_bfloat16 g_hs_hi[(size_t)NTOK * EMB];
__device__ __nv_bfloat16 g_hs_lo[(size_t)NTOK * EMB];
__device__ __nv_bfloat16 g_ao_hi[(size_t)NTOK * EMB];
__device__ __nv_bfloat16 g_ao_lo[(size_t)NTOK * EMB];
__device__ __nv_bfloat16 g_w1t_hi[(size_t)3 * EMB * EMB];  // [N=3072, K=1024]
__device__ __nv_bfloat16 g_w1t_lo[(size_t)3 * EMB * EMB];
__device__ __nv_bfloat16 g_w2t_hi[(size_t)EMB * EMB];      // [N=1024, K=1024]
__device__ __nv_bfloat16 g_w2t_lo[(size_t)EMB * EMB];

// ---------------- warp-MMA helpers ------------------------------------------
__device__ __forceinline__ uint32_t smem_u32(const void* p) {
    uint32_t a;
    asm("{ .reg .u64 t; cvta.to.shared.u64 t, %1; cvt.u32.u64 %0, t; }"
        : "=r"(a) : "l"(p));
    return a;
}
__device__ __forceinline__ void ldsm4(uint32_t& r0, uint32_t& r1,
                                      uint32_t& r2, uint32_t& r3, uint32_t addr) {
    asm volatile("ldmatrix.sync.aligned.m8n8.x4.shared.b16 {%0,%1,%2,%3}, [%4];"
                 : "=r"(r0), "=r"(r1), "=r"(r2), "=r"(r3) : "r"(addr));
}
__device__ __forceinline__ void ldsm4t(uint32_t& r0, uint32_t& r1,
                                       uint32_t& r2, uint32_t& r3, uint32_t addr) {
    asm volatile("ldmatrix.sync.aligned.m8n8.x4.trans.shared.b16 {%0,%1,%2,%3}, [%4];"
                 : "=r"(r0), "=r"(r1), "=r"(r2), "=r"(r3) : "r"(addr));
}
__device__ __forceinline__ void mma16816(float* c, const uint32_t* a,
                                         uint32_t b0, uint32_t b1) {
    asm volatile(
        "mma.sync.aligned.m16n8k16.row.col.f32.bf16.bf16.f32 "
        "{%0,%1,%2,%3}, {%4,%5,%6,%7}, {%8,%9}, {%0,%1,%2,%3};"
        : "+f"(c[0]), "+f"(c[1]), "+f"(c[2]), "+f"(c[3])
        : "r"(a[0]), "r"(a[1]), "r"(a[2]), "r"(a[3]), "r"(b0), "r"(b1));
}
__device__ __forceinline__ void cp16(uint32_t dst, const void* src) {
    asm volatile("cp.async.cg.shared.global [%0], [%1], 16;"
                 :: "r"(dst), "l"(src) : "memory");
}
#define CP_COMMIT() asm volatile("cp.async.commit_group;" ::: "memory")
template<int N>
__device__ __forceinline__ void cp_wait() {
    asm volatile("cp.async.wait_group %0;" :: "n"(N) : "memory");
}

// =============================================================================
// split-bf16 HMMA GEMM (round-10 measured-best variant, double-sync loop).
// =============================================================================
#define SP 40   // smem row pitch (bf16)
#define GEMM_SMEM (2 * 4 * 128 * SP * 2)   // 81920 B

template<int MODE>
__global__ __launch_bounds__(128, 2)
void mma_gemm(const float* __restrict__ bias, float* __restrict__ Cout) {
    extern __shared__ __nv_bfloat16 smg[];

    const int tid = threadIdx.x;
    const int wid = tid >> 5, lane = tid & 31;
    const int K = EMB;
    const int m0 = blockIdx.y * 128;
    const int n0 = blockIdx.x * 128;
    const int wm = wid & 1;
    const int wnw = wid >> 1;

    const __nv_bfloat16* __restrict__ gsrc[4] = {
        MODE ? g_ao_hi : g_hs_hi, MODE ? g_ao_lo : g_hs_lo,
        MODE ? g_w2t_hi : g_w1t_hi, MODE ? g_w2t_lo : g_w1t_lo};
    const int rb[4] = {m0, m0, n0, n0};

    const uint32_t sb = smem_u32(smg);
    const int BUF = 4 * 128 * SP;

    float acc[4][8][4];
#pragma unroll
    for (int i = 0; i < 4; i++)
#pragma unroll
        for (int j = 0; j < 8; j++)
#pragma unroll
            for (int k = 0; k < 4; k++) acc[i][j][k] = 0.f;

    const int grp = lane >> 3, lr = lane & 7;
    const int a_row = ((grp & 1) << 3) + lr;
    const int a_colh = (grp >> 1) << 3;
    const int b_row = ((grp >> 1) << 3) + lr;
    const int b_colh = (grp & 1) << 3;

    auto issue = [&](int t, int buf) {
#pragma unroll
        for (int arr = 0; arr < 4; arr++) {
#pragma unroll
            for (int r = 0; r < 4; r++) {
                int idx = r * 128 + tid;
                int row = idx >> 2, seg = idx & 3;
                cp16(sb + (buf * BUF + arr * 128 * SP + row * SP + seg * 8) * 2,
                     gsrc[arr] + (size_t)(rb[arr] + row) * K + t * 32 + seg * 8);
            }
        }
        CP_COMMIT();
    };

    issue(0, 0);

    const int nt = K / 32;
    for (int t = 0; t < nt; t++) {
        const int buf = t & 1;
        if (t + 1 < nt) { issue(t + 1, buf ^ 1); cp_wait<1>(); }
        else cp_wait<0>();
        __syncthreads();

        const uint32_t base = sb + buf * BUF * 2;
        const uint32_t aofs_hi = base;
        const uint32_t aofs_lo = base + 128 * SP * 2;
        const uint32_t bofs_hi = base + 2 * 128 * SP * 2;
        const uint32_t bofs_lo = base + 3 * 128 * SP * 2;

#pragma unroll
        for (int ks = 0; ks < 2; ks++) {
            const int k0 = ks * 16;
            uint32_t ah[4][4], al[4][4];
#pragma unroll
            for (int ma = 0; ma < 4; ma++) {
                int row = wm * 64 + ma * 16 + a_row;
                ldsm4(ah[ma][0], ah[ma][1], ah[ma][2], ah[ma][3],
                      aofs_hi + (row * SP + k0 + a_colh) * 2);
                ldsm4(al[ma][0], al[ma][1], al[ma][2], al[ma][3],
                      aofs_lo + (row * SP + k0 + a_colh) * 2);
            }
#pragma unroll
            for (int nb = 0; nb < 4; nb++) {
                int row = wnw * 64 + nb * 16 + b_row;
                int col = k0 + b_colh;
                uint32_t bh0, bh1, bh2, bh3, bl0, bl1, bl2, bl3;
                ldsm4(bh0, bh1, bh2, bh3, bofs_hi + (row * SP + col) * 2);
                ldsm4(bl0, bl1, bl2, bl3, bofs_lo + (row * SP + col) * 2);
#pragma unroll
                for (int ma = 0; ma < 4; ma++) {
                    mma16816(acc[ma][nb * 2 + 0], ah[ma], bh0, bh1);
                    mma16816(acc[ma][nb * 2 + 0], ah[ma], bl0, bl1);
                    mma16816(acc[ma][nb * 2 + 0], al[ma], bh0, bh1);
                    mma16816(acc[ma][nb * 2 + 1], ah[ma], bh2, bh3);
                    mma16816(acc[ma][nb * 2 + 1], ah[ma], bl2, bl3);
                    mma16816(acc[ma][nb * 2 + 1], al[ma], bh2, bh3);
                }
            }
        }
        __syncthreads();
    }

    // epilogue
#pragma unroll
    for (int ma = 0; ma < 4; ma++) {
#pragma unroll
        for (int na = 0; na < 8; na++) {
            float* c = acc[ma][na];
            const int gn = n0 + wnw * 64 + na * 8 + ((lane & 3) << 1);
            const float bx = bias[gn], by = bias[gn + 1];
            const int gr0 = m0 + wm * 64 + ma * 16 + (lane >> 2);
            if (MODE == 0) {
                const int which = gn >> 10;
                const int head  = (gn & 1023) >> 6;
                const int d     = gn & 63;
                __nv_bfloat16* dh = (which == 0) ? g_qh : ((which == 1) ? g_kh : g_vh);
                __nv_bfloat16* dl = (which == 0) ? g_ql : ((which == 1) ? g_kl : g_vl);
#pragma unroll
                for (int rr = 0; rr < 2; rr++) {
                    int gr = gr0 + rr * 8;
                    float x = c[rr * 2 + 0] + bx, y = c[rr * 2 + 1] + by;
                    __nv_bfloat162 h2 = __float22bfloat162_rn(make_float2(x, y));
                    __nv_bfloat162 l2 = __float22bfloat162_rn(
                        make_float2(x - __bfloat162float(h2.x),
                                    y - __bfloat162float(h2.y)));
                    size_t o = (((size_t)(gr >> 11) * NH + head) * S_LEN
                                + (gr & 2047)) * HD + d;
                    *(__nv_bfloat162*)&dh[o] = h2;
                    *(__nv_bfloat162*)&dl[o] = l2;
                }
            } else {
#pragma unroll
                for (int rr = 0; rr < 2; rr++) {
                    int gr = gr0 + rr * 8;
                    float2 o = {c[rr * 2 + 0] + bx, c[rr * 2 + 1] + by};
                    *(float2*)&Cout[(size_t)gr * EMB + gn] = o;
                }
            }
        }
    }
}

// =============================================================================
// HMMA causal attention, Q-TILE 128, 256 threads (8 warps: 4m x 2n).
// K/V tiles of 64. kv loop kt = 0 .. 2qt+1; masking on kt >= 2qt.
// 2 CTAs/SM (16 warps) vs previous 12; K/V traffic per flop halved.
// LPT: qt = 15 - blockIdx.x.
// =============================================================================
#define AP 72                                 // smem pitch (bf16)
#define TQ (128 * AP)                         // 128-row tile elems
#define TK (64 * AP)                          // 64-row tile elems
#define ATTN_SMEM ((2 * TQ + 4 * TK + 2 * TQ) * 2)   // 110592 B

__global__ __launch_bounds__(256, 2)
void attn_kernel(float* __restrict__ wout) {
    extern __shared__ __nv_bfloat16 sma[];
    __nv_bfloat16* const Qh = sma;                    // [128][AP]
    __nv_bfloat16* const Ql = sma + TQ;
    __nv_bfloat16* const Kh = sma + 2 * TQ;           // [64][AP]
    __nv_bfloat16* const Kl = sma + 2 * TQ + TK;
    __nv_bfloat16* const Vh = sma + 2 * TQ + 2 * TK;
    __nv_bfloat16* const Vl = sma + 2 * TQ + 3 * TK;
    __nv_bfloat16* const Ph = sma + 2 * TQ + 4 * TK;  // [128][AP]
    __nv_bfloat16* const Pl = sma + 3 * TQ + 4 * TK;

    const int tid = threadIdx.x;
    const int lane = tid & 31, wid = tid >> 5;
    const int wm = wid & 3;                   // m quadrant (32 rows)
    const int wn = wid >> 2;                  // n half
    const int qt = 15 - blockIdx.x;           // LPT
    const int bh = blockIdx.y;
    const int q0 = qt * 128;
    const int b = bh >> 4, h = bh & 15;
    const float scale = 0.125f;

    const size_t hb = (size_t)bh * S_LEN * HD;
    const uint32_t sb = smem_u32(sma);
    const uint32_t uQh = sb, uQl = sb + TQ * 2;
    const uint32_t uKh = sb + (2 * TQ) * 2, uKl = sb + (2 * TQ + TK) * 2;
    const uint32_t uVh = sb + (2 * TQ + 2 * TK) * 2;
    const uint32_t uVl = sb + (2 * TQ + 3 * TK) * 2;
    const uint32_t uPh = sb + (2 * TQ + 4 * TK) * 2;
    const uint32_t uPl = sb + (3 * TQ + 4 * TK) * 2;

    // load Q tile (hi/lo): 128 rows x 64 bf16 => 1024 uint4 per array
#pragma unroll
    for (int i = 0; i < 4; i++) {
        int idx = i * 256 + tid;              // 0..1023
        int row = idx >> 3, seg = idx & 7;
        size_t go = hb + (size_t)(q0 + row) * HD + seg * 8;
        *(uint4*)&Qh[row * AP + seg * 8] = *(const uint4*)&g_qh[go];
        *(uint4*)&Ql[row * AP + seg * 8] = *(const uint4*)&g_ql[go];
    }

    const int grp = lane >> 3, lr = lane & 7;
    const int a_row = ((grp & 1) << 3) + lr;
    const int a_colh = (grp >> 1) << 3;
    const int b_row = ((grp >> 1) << 3) + lr;
    const int b_colh = (grp & 1) << 3;

    float oacc[2][4][4];
#pragma unroll
    for (int i = 0; i < 2; i++)
#pragma unroll
        for (int j = 0; j < 4; j++)
#pragma unroll
            for (int k = 0; k < 4; k++) oacc[i][j][k] = 0.f;
    float lacc[2][2] = {{0.f, 0.f}, {0.f, 0.f}};

    const int ktmax = 2 * qt + 1;
    for (int kt = 0; kt <= ktmax; kt++) {
        __syncthreads();
        // load K/V hi/lo tiles: 64 rows => 512 uint4 per array
#pragma unroll
        for (int i = 0; i < 2; i++) {
            int idx = i * 256 + tid;          // 0..511
            int row = idx >> 3, seg = idx & 7;
            size_t go = hb + (size_t)(kt * 64 + row) * HD + seg * 8;
            *(uint4*)&Kh[row * AP + seg * 8] = *(const uint4*)&g_kh[go];
            *(uint4*)&Kl[row * AP + seg * 8] = *(const uint4*)&g_kl[go];
            *(uint4*)&Vh[row * AP + seg * 8] = *(const uint4*)&g_vh[go];
            *(uint4*)&Vl[row * AP + seg * 8] = *(const uint4*)&g_vl[go];
        }
        __syncthreads();

        // ---------- S = Q K^T  (warp: m 32 x n 32 of kv) ----------
        float sacc[2][4][4];
#pragma unroll
        for (int i = 0; i < 2; i++)
#pragma unroll
            for (int j = 0; j < 4; j++)
#pragma unroll
                for (int k = 0; k < 4; k++) sacc[i][j][k] = 0.f;

#pragma unroll
        for (int kc = 0; kc < 4; kc++) {
            const int k0 = kc * 16;
            uint32_t ah[2][4], al[2][4];
#pragma unroll
            for (int ma = 0; ma < 2; ma++) {
                int row = wm * 32 + ma * 16 + a_row;
                ldsm4(ah[ma][0], ah[ma][1], ah[ma][2], ah[ma][3],
                      uQh + (row * AP + k0 + a_colh) * 2);
                ldsm4(al[ma][0], al[ma][1], al[ma][2], al[ma][3],
                      uQl + (row * AP + k0 + a_colh) * 2);
            }
#pragma unroll
            for (int nb = 0; nb < 2; nb++) {
                int row = wn * 32 + nb * 16 + b_row;
                uint32_t bh0, bh1, bh2, bh3, bl0, bl1, bl2, bl3;
                ldsm4(bh0, bh1, bh2, bh3, uKh + (row * AP + k0 + b_colh) * 2);
                ldsm4(bl0, bl1, bl2, bl3, uKl + (row * AP + k0 + b_colh) * 2);
#pragma unroll
                for (int ma = 0; ma < 2; ma++) {
                    mma16816(sacc[ma][nb * 2 + 0], ah[ma], bh0, bh1);
                    mma16816(sacc[ma][nb * 2 + 0], ah[ma], bl0, bl1);
                    mma16816(sacc[ma][nb * 2 + 0], al[ma], bh0, bh1);
                    mma16816(sacc[ma][nb * 2 + 1], ah[ma], bh2, bh3);
                    mma16816(sacc[ma][nb * 2 + 1], ah[ma], bl2, bl3);
                    mma16816(sacc[ma][nb * 2 + 1], al[ma], bh2, bh3);
                }
            }
        }

        // ---------- exp, raw weights out, P -> smem hi/lo ----------
        const bool diag = (kt >= 2 * qt);
#pragma unroll
        for (int ma = 0; ma < 2; ma++) {
#pragma unroll
            for (int na = 0; na < 4; na++) {
                float* c = sacc[ma][na];
                const int rl0 = wm * 32 + ma * 16 + (lane >> 2);
                const int cl = wn * 32 + na * 8 + ((lane & 3) << 1);
                const int gr0 = q0 + rl0, gc = kt * 64 + cl;
                float e00 = __expf(c[0] * scale);
                float e01 = __expf(c[1] * scale);
                float e10 = __expf(c[2] * scale);
                float e11 = __expf(c[3] * scale);
                if (diag) {
                    if (gc > gr0)     e00 = 0.f;
                    if (gc + 1 > gr0) e01 = 0.f;
                    if (gc > gr0 + 8)     e10 = 0.f;
                    if (gc + 1 > gr0 + 8) e11 = 0.f;
                }
                lacc[ma][0] += e00 + e01;
                lacc[ma][1] += e10 + e11;
                *(float2*)&wout[((size_t)bh * S_LEN + gr0) * S_LEN + gc] =
                    make_float2(e00, e01);
                *(float2*)&wout[((size_t)bh * S_LEN + gr0 + 8) * S_LEN + gc] =
                    make_float2(e10, e11);
                __nv_bfloat162 h0 = __float22bfloat162_rn(make_float2(e00, e01));
                __nv_bfloat162 h1 = __float22bfloat162_rn(make_float2(e10, e11));
                __nv_bfloat162 l0 = __float22bfloat162_rn(
                    make_float2(e00 - __bfloat162float(h0.x),
                                e01 - __bfloat162float(h0.y)));
                __nv_bfloat162 l1 = __float22bfloat162_rn(
                    make_float2(e10 - __bfloat162float(h1.x),
                                e11 - __bfloat162float(h1.y)));
                *(__nv_bfloat162*)&Ph[rl0 * AP + cl] = h0;
                *(__nv_bfloat162*)&Ph[(rl0 + 8) * AP + cl] = h1;
                *(__nv_bfloat162*)&Pl[rl0 * AP + cl] = l0;
                *(__nv_bfloat162*)&Pl[(rl0 + 8) * AP + cl] = l1;
            }
        }
        __syncthreads();

        // ---------- O += P V  (warp: m 32 x d 32 half) ----------
#pragma unroll
        for (int kc = 0; kc < 4; kc++) {
            const int k0 = kc * 16;
            uint32_t ph[2][4], pl[2][4];
#pragma unroll
            for (int ma = 0; ma < 2; ma++) {
                int row = wm * 32 + ma * 16 + a_row;
                ldsm4(ph[ma][0], ph[ma][1], ph[ma][2], ph[ma][3],
                      uPh + (row * AP + k0 + a_colh) * 2);
                ldsm4(pl[ma][0], pl[ma][1], pl[ma][2], pl[ma][3],
                      uPl + (row * AP + k0 + a_colh) * 2);
            }
#pragma unroll
            for (int ndl = 0; ndl < 2; ndl++) {
                int vrow = k0 + ((grp & 1) << 3) + lr;
                int vcol = wn * 32 + ndl * 16 + ((grp >> 1) << 3);
                uint32_t vh0, vh1, vh2, vh3, vl0, vl1, vl2, vl3;
                ldsm4t(vh0, vh1, vh2, vh3, uVh + (vrow * AP + vcol) * 2);
                ldsm4t(vl0, vl1, vl2, vl3, uVl + (vrow * AP + vcol) * 2);
#pragma unroll
                for (int ma = 0; ma < 2; ma++) {
                    mma16816(oacc[ma][ndl * 2 + 0], ph[ma], vh0, vh1);
                    mma16816(oacc[ma][ndl * 2 + 0], ph[ma], vl0, vl1);
                    mma16816(oacc[ma][ndl * 2 + 0], pl[ma], vh0, vh1);
                    mma16816(oacc[ma][ndl * 2 + 1], ph[ma], vh2, vh3);
                    mma16816(oacc[ma][ndl * 2 + 1], ph[ma], vl2, vl3);
                    mma16816(oacc[ma][ndl * 2 + 1], pl[ma], vh2, vh3);
                }
            }
        }
    }

    // zero-fill fully-masked upper region (d_out poisoned)
    {
        const int ce = (qt + 1) * 128;
        const int n4 = (S_LEN - ce) >> 2;
        if (n4 > 0) {
            const float4 z = {0.f, 0.f, 0.f, 0.f};
            for (int i = tid; i < 128 * n4; i += 256) {
                int r = i / n4, c = i - r * n4;
                *(float4*)&wout[((size_t)bh * S_LEN + q0 + r) * S_LEN + ce + c * 4] = z;
            }
        }
    }

    // ---------- l reduction ----------
    __syncthreads();
    float* fs = (float*)sma;

#pragma unroll
    for (int ma = 0; ma < 2; ma++) {
#pragma unroll
        for (int half = 0; half < 2; half++) {
            float v = lacc[ma][half];
            v += __shfl_xor_sync(0xffffffffu, v, 1);
            v += __shfl_xor_sync(0xffffffffu, v, 2);
            if ((lane & 3) == 0)
                fs[wn * 128 + wm * 32 + ma * 16 + half * 8 + (lane >> 2)] = v;
        }
    }
    __syncthreads();
    if (tid < 128) {
        float inv = 1.f / (fs[tid] + fs[128 + tid]);
        fs[256 + tid] = inv;
        g_linv[(size_t)bh * S_LEN + q0 + tid] = inv;
    }
    __syncthreads();

    // ---------- normalized O -> g_ao hi/lo ----------
#pragma unroll
    for (int ma = 0; ma < 2; ma++)
#pragma unroll
        for (int nd = 0; nd < 4; nd++) {
            float* c = oacc[ma][nd];
            int rl0 = wm * 32 + ma * 16 + (lane >> 2);
            int d0 = wn * 32 + nd * 8 + ((lane & 3) << 1);
#pragma unroll
            for (int rr = 0; rr < 2; rr++) {
                int rl = rl0 + rr * 8;
                float inv = fs[256 + rl];
                float x = c[rr * 2 + 0] * inv, y = c[rr * 2 + 1] * inv;
                __nv_bfloat162 h2 = __float22bfloat162_rn(make_float2(x, y));
                __nv_bfloat162 l2 = __float22bfloat162_rn(
                    make_float2(x - __bfloat162float(h2.x),
                                y - __bfloat162float(h2.y)));
                size_t tok = (size_t)b * S_LEN + q0 + rl;
                *(__nv_bfloat162*)&g_ao_hi[tok * EMB + h * HD + d0] = h2;
                *(__nv_bfloat162*)&g_ao_lo[tok * EMB + h * HD + d0] = l2;
            }
        }
}

// =============================================================================
// fp32 hidden_states -> (hi, lo) bf16 split.
// =============================================================================
__global__ void split_kernel(const float* __restrict__ src) {
    const size_t i4 = (size_t)blockIdx.x * blockDim.x + threadIdx.x;
    float4 v = ((const float4*)src)[i4];
    float f[4] = {v.x, v.y, v.z, v.w};
    __nv_bfloat16 h[4], l[4];
#pragma unroll
    for (int j = 0; j < 4; j++) {
        h[j] = __float2bfloat16(f[j]);
        l[j] = __float2bfloat16(f[j] - __bfloat162float(h[j]));
    }
    *(uint2*)&g_hs_hi[i4 * 4] = *(uint2*)h;
    *(uint2*)&g_hs_lo[i4 * 4] = *(uint2*)l;
}

// =============================================================================
// W [K,N] fp32 -> Wt_{hi,lo} [N,K] bf16.
// =============================================================================
template<int WHICH>
__global__ void transpose_split_kernel(const float* __restrict__ W, int N) {
    __shared__ float t[32][33];
    __nv_bfloat16* hi = WHICH ? g_w2t_hi : g_w1t_hi;
    __nv_bfloat16* lo = WHICH ? g_w2t_lo : g_w1t_lo;
    const int K = EMB;
    const int nx = blockIdx.x * 32, ky = blockIdx.y * 32;
    const int tx = threadIdx.x, ty = threadIdx.y;
#pragma unroll
    for (int i = 0; i < 4; i++)
        t[ty + i * 8][tx] = W[(size_t)(ky + ty + i * 8) * N + nx + tx];
    __syncthreads();
#pragma unroll
    for (int i = 0; i < 4; i++) {
        float v = t[tx][ty + i * 8];
        __nv_bfloat16 hh = __float2bfloat16(v);
        __nv_bfloat16 ll = __float2bfloat16(v - __bfloat162float(hh));
        size_t o = (size_t)(nx + ty + i * 8) * K + ky + tx;
        hi[o] = hh;
        lo[o] = ll;
    }
}

// =============================================================================
__global__ void rescale_kernel(float* __restrict__ wout) {
    const int row = blockIdx.x;
    const int s = row & (S_LEN - 1);
    const float inv = g_linv[row];
    float4* p = (float4*)(wout + (size_t)row * S_LEN);
    const int n4 = (s + 4) >> 2;
    for (int i = threadIdx.x; i < n4; i += blockDim.x) {
        float4 v = p[i];
        v.x *= inv; v.y *= inv; v.z *= inv; v.w *= inv;
        p[i] = v;
    }
}

// =============================================================================
extern "C" void kernel_launch(void* const* d_in, const int* in_sizes, int n_in,
                              void* d_out, int out_size) {
    const float* hs = (const float*)d_in[0];
    const float* w1 = (const float*)d_in[1];
    const float* b1 = (const float*)d_in[2];
    const float* w2 = (const float*)d_in[3];
    const float* b2 = (const float*)d_in[4];

    float* out = (float*)d_out;
    float* attn_out = out;                           // [B,S,E]
    float* wts = out + (size_t)NTOK * EMB;           // [B,H,S,S]

    cudaFuncSetAttribute(mma_gemm<0>,
                         cudaFuncAttributeMaxDynamicSharedMemorySize, GEMM_SMEM);
    cudaFuncSetAttribute(mma_gemm<1>,
                         cudaFuncAttributeMaxDynamicSharedMemorySize, GEMM_SMEM);
    cudaFuncSetAttribute(attn_kernel,
                         cudaFuncAttributeMaxDynamicSharedMemorySize, ATTN_SMEM);

    // side stream + events for graph-captured fork/join
    cudaStream_t s2;
    cudaStreamCreateWithFlags(&s2, cudaStreamNonBlocking);
    cudaEvent_t ev0, ev1, evw2, ev2, ev3;
    cudaEventCreateWithFlags(&ev0, cudaEventDisableTiming);
    cudaEventCreateWithFlags(&ev1, cudaEventDisableTiming);
    cudaEventCreateWithFlags(&evw2, cudaEventDisableTiming);
    cudaEventCreateWithFlags(&ev2, cudaEventDisableTiming);
    cudaEventCreateWithFlags(&ev3, cudaEventDisableTiming);

    // ---- fork 1: w1/w2 transposes (s2)  ||  hs split (main) ----
    cudaEventRecord(ev0, 0);
    cudaStreamWaitEvent(s2, ev0, 0);
    transpose_split_kernel<0><<<dim3(96, 32), dim3(32, 8), 0, s2>>>(w1, 3 * EMB);
    cudaEventRecord(ev1, s2);                       // qkv gate: w1t ready
    transpose_split_kernel<1><<<dim3(32, 32), dim3(32, 8), 0, s2>>>(w2, EMB);
    cudaEventRecord(evw2, s2);                      // proj gate: w2t ready

    split_kernel<<<(NTOK * EMB / 4) / 256, 256>>>(hs);
    cudaStreamWaitEvent(0, ev1, 0);

    // ---- main chain ----
    mma_gemm<0><<<dim3(24, 32), 128, GEMM_SMEM>>>(b1, nullptr);
    attn_kernel<<<dim3(16, 32), 256, ATTN_SMEM>>>(wts);

    // ---- fork 2: rescale (s2, DRAM-bound)  ||  proj (main, tensor-bound) ----
    cudaEventRecord(ev2, 0);
    cudaStreamWaitEvent(s2, ev2, 0);
    rescale_kernel<<<NB * NH * S_LEN, 128, 0, s2>>>(wts);
    cudaEventRecord(ev3, s2);

    cudaStreamWaitEvent(0, evw2, 0);
    mma_gemm<1><<<dim3(8, 32), 128, GEMM_SMEM>>>(b2, attn_out);
    cudaStreamWaitEvent(0, ev3, 0);                 // join
}

// round 13
// speedup vs baseline: 1.0177x; 1.0177x over previous
#include <cuda_runtime.h>
#include <cuda_bf16.h>
#include <float.h>
#include <math.h>
#include <stdint.h>

#define S_LEN 2048
#define EMB   1024
#define NH    16
#define HD    64
#define NB    2
#define NTOK  (NB * S_LEN)   // 4096

// ---------------- scratch (device globals: no allocation allowed) ------------
__device__ float g_linv[(size_t)NB * NH * S_LEN];     // per-row 1/l

__device__ __nv_bfloat16 g_qh[(size_t)NB * NH * S_LEN * HD];  // [B,H,S,D]
__device__ __nv_bfloat16 g_ql[(size_t)NB * NH * S_LEN * HD];
__device__ __nv_bfloat16 g_kh[(size_t)NB * NH * S_LEN * HD];
__device__ __nv_bfloat16 g_kl[(size_t)NB * NH * S_LEN * HD];
__device__ __nv_bfloat16 g_vh[(size_t)NB * NH * S_LEN * HD];
__device__ __nv_bfloat16 g_vl[(size_t)NB * NH * S_LEN * HD];
__device__ __nv_bfloat16 g_hs_hi[(size_t)NTOK * EMB];
__device__ __nv_bfloat16 g_hs_lo[(size_t)NTOK * EMB];
__device__ __nv_bfloat16 g_ao_hi[(size_t)NTOK * EMB];
__device__ __nv_bfloat16 g_ao_lo[(size_t)NTOK * EMB];
__device__ __nv_bfloat16 g_w1t_hi[(size_t)3 * EMB * EMB];  // [N=3072, K=1024]
__device__ __nv_bfloat16 g_w1t_lo[(size_t)3 * EMB * EMB];
__device__ __nv_bfloat16 g_w2t_hi[(size_t)EMB * EMB];      // [N=1024, K=1024]
__device__ __nv_bfloat16 g_w2t_lo[(size_t)EMB * EMB];

// ---------------- warp-MMA helpers ------------------------------------------
__device__ __forceinline__ uint32_t smem_u32(const void* p) {
    uint32_t a;
    asm("{ .reg .u64 t; cvta.to.shared.u64 t, %1; cvt.u32.u64 %0, t; }"
        : "=r"(a) : "l"(p));
    return a;
}
__device__ __forceinline__ void ldsm4(uint32_t& r0, uint32_t& r1,
                                      uint32_t& r2, uint32_t& r3, uint32_t addr) {
    asm volatile("ldmatrix.sync.aligned.m8n8.x4.shared.b16 {%0,%1,%2,%3}, [%4];"
                 : "=r"(r0), "=r"(r1), "=r"(r2), "=r"(r3) : "r"(addr));
}
__device__ __forceinline__ void ldsm4t(uint32_t& r0, uint32_t& r1,
                                       uint32_t& r2, uint32_t& r3, uint32_t addr) {
    asm volatile("ldmatrix.sync.aligned.m8n8.x4.trans.shared.b16 {%0,%1,%2,%3}, [%4];"
                 : "=r"(r0), "=r"(r1), "=r"(r2), "=r"(r3) : "r"(addr));
}
__device__ __forceinline__ void mma16816(float* c, const uint32_t* a,
                                         uint32_t b0, uint32_t b1) {
    asm volatile(
        "mma.sync.aligned.m16n8k16.row.col.f32.bf16.bf16.f32 "
        "{%0,%1,%2,%3}, {%4,%5,%6,%7}, {%8,%9}, {%0,%1,%2,%3};"
        : "+f"(c[0]), "+f"(c[1]), "+f"(c[2]), "+f"(c[3])
        : "r"(a[0]), "r"(a[1]), "r"(a[2]), "r"(a[3]), "r"(b0), "r"(b1));
}
__device__ __forceinline__ void cp16(uint32_t dst, const void* src) {
    asm volatile("cp.async.cg.shared.global [%0], [%1], 16;"
                 :: "r"(dst), "l"(src) : "memory");
}
#define CP_COMMIT() asm volatile("cp.async.commit_group;" ::: "memory")
template<int N>
__device__ __forceinline__ void cp_wait() {
    asm volatile("cp.async.wait_group %0;" :: "n"(N) : "memory");
}

// =============================================================================
// split-bf16 HMMA GEMM (round-10 measured-best variant, unchanged).
// =============================================================================
#define SP 40   // smem row pitch (bf16)
#define GEMM_SMEM (2 * 4 * 128 * SP * 2)   // 81920 B

template<int MODE>
__global__ __launch_bounds__(128, 2)
void mma_gemm(const float* __restrict__ bias, float* __restrict__ Cout) {
    extern __shared__ __nv_bfloat16 smg[];

    const int tid = threadIdx.x;
    const int wid = tid >> 5, lane = tid & 31;
    const int K = EMB;
    const int m0 = blockIdx.y * 128;
    const int n0 = blockIdx.x * 128;
    const int wm = wid & 1;
    const int wnw = wid >> 1;

    const __nv_bfloat16* __restrict__ gsrc[4] = {
        MODE ? g_ao_hi : g_hs_hi, MODE ? g_ao_lo : g_hs_lo,
        MODE ? g_w2t_hi : g_w1t_hi, MODE ? g_w2t_lo : g_w1t_lo};
    const int rb[4] = {m0, m0, n0, n0};

    const uint32_t sb = smem_u32(smg);
    const int BUF = 4 * 128 * SP;

    float acc[4][8][4];
#pragma unroll
    for (int i = 0; i < 4; i++)
#pragma unroll
        for (int j = 0; j < 8; j++)
#pragma unroll
            for (int k = 0; k < 4; k++) acc[i][j][k] = 0.f;

    const int grp = lane >> 3, lr = lane & 7;
    const int a_row = ((grp & 1) << 3) + lr;
    const int a_colh = (grp >> 1) << 3;
    const int b_row = ((grp >> 1) << 3) + lr;
    const int b_colh = (grp & 1) << 3;

    auto issue = [&](int t, int buf) {
#pragma unroll
        for (int arr = 0; arr < 4; arr++) {
#pragma unroll
            for (int r = 0; r < 4; r++) {
                int idx = r * 128 + tid;
                int row = idx >> 2, seg = idx & 3;
                cp16(sb + (buf * BUF + arr * 128 * SP + row * SP + seg * 8) * 2,
                     gsrc[arr] + (size_t)(rb[arr] + row) * K + t * 32 + seg * 8);
            }
        }
        CP_COMMIT();
    };

    issue(0, 0);

    const int nt = K / 32;
    for (int t = 0; t < nt; t++) {
        const int buf = t & 1;
        if (t + 1 < nt) { issue(t + 1, buf ^ 1); cp_wait<1>(); }
        else cp_wait<0>();
        __syncthreads();

        const uint32_t base = sb + buf * BUF * 2;
        const uint32_t aofs_hi = base;
        const uint32_t aofs_lo = base + 128 * SP * 2;
        const uint32_t bofs_hi = base + 2 * 128 * SP * 2;
        const uint32_t bofs_lo = base + 3 * 128 * SP * 2;

#pragma unroll
        for (int ks = 0; ks < 2; ks++) {
            const int k0 = ks * 16;
            uint32_t ah[4][4], al[4][4];
#pragma unroll
            for (int ma = 0; ma < 4; ma++) {
                int row = wm * 64 + ma * 16 + a_row;
                ldsm4(ah[ma][0], ah[ma][1], ah[ma][2], ah[ma][3],
                      aofs_hi + (row * SP + k0 + a_colh) * 2);
                ldsm4(al[ma][0], al[ma][1], al[ma][2], al[ma][3],
                      aofs_lo + (row * SP + k0 + a_colh) * 2);
            }
#pragma unroll
            for (int nb = 0; nb < 4; nb++) {
                int row = wnw * 64 + nb * 16 + b_row;
                int col = k0 + b_colh;
                uint32_t bh0, bh1, bh2, bh3, bl0, bl1, bl2, bl3;
                ldsm4(bh0, bh1, bh2, bh3, bofs_hi + (row * SP + col) * 2);
                ldsm4(bl0, bl1, bl2, bl3, bofs_lo + (row * SP + col) * 2);
#pragma unroll
                for (int ma = 0; ma < 4; ma++) {
                    mma16816(acc[ma][nb * 2 + 0], ah[ma], bh0, bh1);
                    mma16816(acc[ma][nb * 2 + 0], ah[ma], bl0, bl1);
                    mma16816(acc[ma][nb * 2 + 0], al[ma], bh0, bh1);
                    mma16816(acc[ma][nb * 2 + 1], ah[ma], bh2, bh3);
                    mma16816(acc[ma][nb * 2 + 1], ah[ma], bl2, bl3);
                    mma16816(acc[ma][nb * 2 + 1], al[ma], bh2, bh3);
                }
            }
        }
        __syncthreads();
    }

    // epilogue
#pragma unroll
    for (int ma = 0; ma < 4; ma++) {
#pragma unroll
        for (int na = 0; na < 8; na++) {
            float* c = acc[ma][na];
            const int gn = n0 + wnw * 64 + na * 8 + ((lane & 3) << 1);
            const float bx = bias[gn], by = bias[gn + 1];
            const int gr0 = m0 + wm * 64 + ma * 16 + (lane >> 2);
            if (MODE == 0) {
                const int which = gn >> 10;
                const int head  = (gn & 1023) >> 6;
                const int d     = gn & 63;
                __nv_bfloat16* dh = (which == 0) ? g_qh : ((which == 1) ? g_kh : g_vh);
                __nv_bfloat16* dl = (which == 0) ? g_ql : ((which == 1) ? g_kl : g_vl);
#pragma unroll
                for (int rr = 0; rr < 2; rr++) {
                    int gr = gr0 + rr * 8;
                    float x = c[rr * 2 + 0] + bx, y = c[rr * 2 + 1] + by;
                    __nv_bfloat162 h2 = __float22bfloat162_rn(make_float2(x, y));
                    __nv_bfloat162 l2 = __float22bfloat162_rn(
                        make_float2(x - __bfloat162float(h2.x),
                                    y - __bfloat162float(h2.y)));
                    size_t o = (((size_t)(gr >> 11) * NH + head) * S_LEN
                                + (gr & 2047)) * HD + d;
                    *(__nv_bfloat162*)&dh[o] = h2;
                    *(__nv_bfloat162*)&dl[o] = l2;
                }
            } else {
#pragma unroll
                for (int rr = 0; rr < 2; rr++) {
                    int gr = gr0 + rr * 8;
                    float2 o = {c[rr * 2 + 0] + bx, c[rr * 2 + 1] + by};
                    *(float2*)&Cout[(size_t)gr * EMB + gn] = o;
                }
            }
        }
    }
}

// =============================================================================
// HMMA causal attention (round-10 version, MINUS the zero-fill epilogue —
// the upper-triangle zeros are written by zero_fill_kernel concurrent with
// the qkv GEMM instead).
// =============================================================================
#define AP 72
#define T64 (64 * AP)
#define ATTN_SMEM (8 * T64 * 2)              // 73728 B

__global__ __launch_bounds__(128, 3)
void attn_kernel(float* __restrict__ wout) {
    extern __shared__ __nv_bfloat16 sma[];
    __nv_bfloat16* const Qh = sma;
    __nv_bfloat16* const Ql = sma + T64;
    __nv_bfloat16* const Kh = sma + 2 * T64;
    __nv_bfloat16* const Kl = sma + 3 * T64;
    __nv_bfloat16* const Vh = sma + 4 * T64;
    __nv_bfloat16* const Vl = sma + 5 * T64;
    __nv_bfloat16* const Ph = sma + 6 * T64;
    __nv_bfloat16* const Pl = sma + 7 * T64;

    const int tid = threadIdx.x;
    const int lane = tid & 31, wid = tid >> 5;
    const int wm = wid & 1, wn = wid >> 1;
    const int qt = blockIdx.x, bh = blockIdx.y;
    const int q0 = qt * 64;
    const int b = bh >> 4, h = bh & 15;
    const float scale = 0.125f;

    const size_t hb = (size_t)bh * S_LEN * HD;
    const uint32_t sb = smem_u32(sma);
    const uint32_t uQh = sb, uQl = sb + T64 * 2;
    const uint32_t uKh = sb + 2 * T64 * 2, uKl = sb + 3 * T64 * 2;
    const uint32_t uVh = sb + 4 * T64 * 2, uVl = sb + 5 * T64 * 2;
    const uint32_t uPh = sb + 6 * T64 * 2, uPl = sb + 7 * T64 * 2;

#pragma unroll
    for (int i = 0; i < 4; i++) {
        int idx = i * 128 + tid;
        int row = idx >> 3, seg = idx & 7;
        size_t go = hb + (size_t)(q0 + row) * HD + seg * 8;
        *(uint4*)&Qh[row * AP + seg * 8] = *(const uint4*)&g_qh[go];
        *(uint4*)&Ql[row * AP + seg * 8] = *(const uint4*)&g_ql[go];
    }

    const int grp = lane >> 3, lr = lane & 7;
    const int a_row = ((grp & 1) << 3) + lr;
    const int a_colh = (grp >> 1) << 3;
    const int b_row = ((grp >> 1) << 3) + lr;
    const int b_colh = (grp & 1) << 3;

    float oacc[2][4][4];
#pragma unroll
    for (int i = 0; i < 2; i++)
#pragma unroll
        for (int j = 0; j < 4; j++)
#pragma unroll
            for (int k = 0; k < 4; k++) oacc[i][j][k] = 0.f;
    float lacc[2][2] = {{0.f, 0.f}, {0.f, 0.f}};

    for (int kt = 0; kt <= qt; kt++) {
        __syncthreads();
#pragma unroll
        for (int i = 0; i < 4; i++) {
            int idx = i * 128 + tid;
            int row = idx >> 3, seg = idx & 7;
            size_t go = hb + (size_t)(kt * 64 + row) * HD + seg * 8;
            *(uint4*)&Kh[row * AP + seg * 8] = *(const uint4*)&g_kh[go];
            *(uint4*)&Kl[row * AP + seg * 8] = *(const uint4*)&g_kl[go];
            *(uint4*)&Vh[row * AP + seg * 8] = *(const uint4*)&g_vh[go];
            *(uint4*)&Vl[row * AP + seg * 8] = *(const uint4*)&g_vl[go];
        }
        __syncthreads();

        // ---------- S = Q K^T ----------
        float sacc[2][4][4];
#pragma unroll
        for (int i = 0; i < 2; i++)
#pragma unroll
            for (int j = 0; j < 4; j++)
#pragma unroll
                for (int k = 0; k < 4; k++) sacc[i][j][k] = 0.f;

#pragma unroll
        for (int kc = 0; kc < 4; kc++) {
            const int k0 = kc * 16;
            uint32_t ah[2][4], al[2][4];
#pragma unroll
            for (int ma = 0; ma < 2; ma++) {
                int row = wm * 32 + ma * 16 + a_row;
                ldsm4(ah[ma][0], ah[ma][1], ah[ma][2], ah[ma][3],
                      uQh + (row * AP + k0 + a_colh) * 2);
                ldsm4(al[ma][0], al[ma][1], al[ma][2], al[ma][3],
                      uQl + (row * AP + k0 + a_colh) * 2);
            }
#pragma unroll
            for (int nb = 0; nb < 2; nb++) {
                int row = wn * 32 + nb * 16 + b_row;
                uint32_t bh0, bh1, bh2, bh3, bl0, bl1, bl2, bl3;
                ldsm4(bh0, bh1, bh2, bh3, uKh + (row * AP + k0 + b_colh) * 2);
                ldsm4(bl0, bl1, bl2, bl3, uKl + (row * AP + k0 + b_colh) * 2);
#pragma unroll
                for (int ma = 0; ma < 2; ma++) {
                    mma16816(sacc[ma][nb * 2 + 0], ah[ma], bh0, bh1);
                    mma16816(sacc[ma][nb * 2 + 0], ah[ma], bl0, bl1);
                    mma16816(sacc[ma][nb * 2 + 0], al[ma], bh0, bh1);
                    mma16816(sacc[ma][nb * 2 + 1], ah[ma], bh2, bh3);
                    mma16816(sacc[ma][nb * 2 + 1], ah[ma], bl2, bl3);
                    mma16816(sacc[ma][nb * 2 + 1], al[ma], bh2, bh3);
                }
            }
        }

        // ---------- exp, raw weights out, P -> smem hi/lo ----------
        const bool diag = (kt == qt);
#pragma unroll
        for (int ma = 0; ma < 2; ma++) {
#pragma unroll
            for (int na = 0; na < 4; na++) {
                float* c = sacc[ma][na];
                const int rl0 = wm * 32 + ma * 16 + (lane >> 2);
                const int cl = wn * 32 + na * 8 + ((lane & 3) << 1);
                const int gr0 = q0 + rl0, gc = kt * 64 + cl;
                float e00 = __expf(c[0] * scale);
                float e01 = __expf(c[1] * scale);
                float e10 = __expf(c[2] * scale);
                float e11 = __expf(c[3] * scale);
                if (diag) {
                    if (gc > gr0)     e00 = 0.f;
                    if (gc + 1 > gr0) e01 = 0.f;
                    if (gc > gr0 + 8)     e10 = 0.f;
                    if (gc + 1 > gr0 + 8) e11 = 0.f;
                }
                lacc[ma][0] += e00 + e01;
                lacc[ma][1] += e10 + e11;
                *(float2*)&wout[((size_t)bh * S_LEN + gr0) * S_LEN + gc] =
                    make_float2(e00, e01);
                *(float2*)&wout[((size_t)bh * S_LEN + gr0 + 8) * S_LEN + gc] =
                    make_float2(e10, e11);
                __nv_bfloat162 h0 = __float22bfloat162_rn(make_float2(e00, e01));
                __nv_bfloat162 h1 = __float22bfloat162_rn(make_float2(e10, e11));
                __nv_bfloat162 l0 = __float22bfloat162_rn(
                    make_float2(e00 - __bfloat162float(h0.x),
                                e01 - __bfloat162float(h0.y)));
                __nv_bfloat162 l1 = __float22bfloat162_rn(
                    make_float2(e10 - __bfloat162float(h1.x),
                                e11 - __bfloat162float(h1.y)));
                *(__nv_bfloat162*)&Ph[rl0 * AP + cl] = h0;
                *(__nv_bfloat162*)&Ph[(rl0 + 8) * AP + cl] = h1;
                *(__nv_bfloat162*)&Pl[rl0 * AP + cl] = l0;
                *(__nv_bfloat162*)&Pl[(rl0 + 8) * AP + cl] = l1;
            }
        }
        __syncthreads();

        // ---------- O += P V ----------
#pragma unroll
        for (int kc = 0; kc < 4; kc++) {
            const int k0 = kc * 16;
            uint32_t ph[2][4], pl[2][4];
#pragma unroll
            for (int ma = 0; ma < 2; ma++) {
                int row = wm * 32 + ma * 16 + a_row;
                ldsm4(ph[ma][0], ph[ma][1], ph[ma][2], ph[ma][3],
                      uPh + (row * AP + k0 + a_colh) * 2);
                ldsm4(pl[ma][0], pl[ma][1], pl[ma][2], pl[ma][3],
                      uPl + (row * AP + k0 + a_colh) * 2);
            }
#pragma unroll
            for (int ndl = 0; ndl < 2; ndl++) {
                int vrow = k0 + ((grp & 1) << 3) + lr;
                int vcol = wn * 32 + ndl * 16 + ((grp >> 1) << 3);
                uint32_t vh0, vh1, vh2, vh3, vl0, vl1, vl2, vl3;
                ldsm4t(vh0, vh1, vh2, vh3, uVh + (vrow * AP + vcol) * 2);
                ldsm4t(vl0, vl1, vl2, vl3, uVl + (vrow * AP + vcol) * 2);
#pragma unroll
                for (int ma = 0; ma < 2; ma++) {
                    mma16816(oacc[ma][ndl * 2 + 0], ph[ma], vh0, vh1);
                    mma16816(oacc[ma][ndl * 2 + 0], ph[ma], vl0, vl1);
                    mma16816(oacc[ma][ndl * 2 + 0], pl[ma], vh0, vh1);
                    mma16816(oacc[ma][ndl * 2 + 1], ph[ma], vh2, vh3);
                    mma16816(oacc[ma][ndl * 2 + 1], ph[ma], vl2, vl3);
                    mma16816(oacc[ma][ndl * 2 + 1], pl[ma], vh2, vh3);
                }
            }
        }
    }

    // (zero-fill of the masked upper region moved to zero_fill_kernel)

    // ---------- l reduction ----------
    __syncthreads();
    float* fs = (float*)sma;

#pragma unroll
    for (int ma = 0; ma < 2; ma++) {
#pragma unroll
        for (int half = 0; half < 2; half++) {
            float v = lacc[ma][half];
            v += __shfl_xor_sync(0xffffffffu, v, 1);
            v += __shfl_xor_sync(0xffffffffu, v, 2);
            if ((lane & 3) == 0)
                fs[wn * 64 + wm * 32 + ma * 16 + half * 8 + (lane >> 2)] = v;
        }
    }
    __syncthreads();
    if (tid < 64) {
        float inv = 1.f / (fs[tid] + fs[64 + tid]);
        fs[128 + tid] = inv;
        g_linv[(size_t)bh * S_LEN + q0 + tid] = inv;
    }
    __syncthreads();

    // ---------- normalized O -> g_ao hi/lo ----------
#pragma unroll
    for (int ma = 0; ma < 2; ma++)
#pragma unroll
        for (int nd = 0; nd < 4; nd++) {
            float* c = oacc[ma][nd];
            int rl0 = wm * 32 + ma * 16 + (lane >> 2);
            int d0 = wn * 32 + nd * 8 + ((lane & 3) << 1);
#pragma unroll
            for (int rr = 0; rr < 2; rr++) {
                int rl = rl0 + rr * 8;
                float inv = fs[128 + rl];
                float x = c[rr * 2 + 0] * inv, y = c[rr * 2 + 1] * inv;
                __nv_bfloat162 h2 = __float22bfloat162_rn(make_float2(x, y));
                __nv_bfloat162 l2 = __float22bfloat162_rn(
                    make_float2(x - __bfloat162float(h2.x),
                                y - __bfloat162float(h2.y)));
                size_t tok = (size_t)b * S_LEN + q0 + rl;
                *(__nv_bfloat162*)&g_ao_hi[tok * EMB + h * HD + d0] = h2;
                *(__nv_bfloat162*)&g_ao_lo[tok * EMB + h * HD + d0] = l2;
            }
        }
}

// =============================================================================
// Zero-fill of the fully-masked weight region: row r gets zeros in cols
// [ce, 2048) where ce = (floor(s/64)+1)*64. Runs on s2 concurrent with the
// qkv GEMM (whose DRAM is idle). Disjoint from all attn + rescale writes.
// =============================================================================
__global__ void zero_fill_kernel(float* __restrict__ wout) {
    const int row = blockIdx.x;                  // 0 .. B*H*S-1
    const int s = row & (S_LEN - 1);
    const int ce = ((s >> 6) + 1) << 6;          // 64-aligned
    const int n4 = (S_LEN - ce) >> 2;
    if (n4 <= 0) return;
    float4* p = (float4*)(wout + (size_t)row * S_LEN + ce);
    const float4 z = {0.f, 0.f, 0.f, 0.f};
    for (int i = threadIdx.x; i < n4; i += blockDim.x) p[i] = z;
}

// =============================================================================
// fp32 hidden_states -> (hi, lo) bf16 split.
// =============================================================================
__global__ void split_kernel(const float* __restrict__ src) {
    const size_t i4 = (size_t)blockIdx.x * blockDim.x + threadIdx.x;
    float4 v = ((const float4*)src)[i4];
    float f[4] = {v.x, v.y, v.z, v.w};
    __nv_bfloat16 h[4], l[4];
#pragma unroll
    for (int j = 0; j < 4; j++) {
        h[j] = __float2bfloat16(f[j]);
        l[j] = __float2bfloat16(f[j] - __bfloat162float(h[j]));
    }
    *(uint2*)&g_hs_hi[i4 * 4] = *(uint2*)h;
    *(uint2*)&g_hs_lo[i4 * 4] = *(uint2*)l;
}

// =============================================================================
// W [K,N] fp32 -> Wt_{hi,lo} [N,K] bf16.
// =============================================================================
template<int WHICH>
__global__ void transpose_split_kernel(const float* __restrict__ W, int N) {
    __shared__ float t[32][33];
    __nv_bfloat16* hi = WHICH ? g_w2t_hi : g_w1t_hi;
    __nv_bfloat16* lo = WHICH ? g_w2t_lo : g_w1t_lo;
    const int K = EMB;
    const int nx = blockIdx.x * 32, ky = blockIdx.y * 32;
    const int tx = threadIdx.x, ty = threadIdx.y;
#pragma unroll
    for (int i = 0; i < 4; i++)
        t[ty + i * 8][tx] = W[(size_t)(ky + ty + i * 8) * N + nx + tx];
    __syncthreads();
#pragma unroll
    for (int i = 0; i < 4; i++) {
        float v = t[tx][ty + i * 8];
        __nv_bfloat16 hh = __float2bfloat16(v);
        __nv_bfloat16 ll = __float2bfloat16(v - __bfloat162float(hh));
        size_t o = (size_t)(nx + ty + i * 8) * K + ky + tx;
        hi[o] = hh;
        lo[o] = ll;
    }
}

// =============================================================================
// Rescale raw exp weights by 1/l — EXACT extent (full float4s + scalar tail
// ending at col s) so it never touches the zero_fill region.
// =============================================================================
__global__ void rescale_kernel(float* __restrict__ wout) {
    const int row = blockIdx.x;
    const int s = row & (S_LEN - 1);
    const float inv = g_linv[row];
    float* rp = wout + (size_t)row * S_LEN;
    float4* p = (float4*)rp;
    const int nfull = (s + 1) >> 2;              // full float4s in cols 0..s
    for (int i = threadIdx.x; i < nfull; i += blockDim.x) {
        float4 v = p[i];
        v.x *= inv; v.y *= inv; v.z *= inv; v.w *= inv;
        p[i] = v;
    }
    const int tail0 = nfull << 2;
    const int ntail = (s + 1) - tail0;           // 0..3 scalar cols
    if (threadIdx.x < ntail) rp[tail0 + threadIdx.x] *= inv;
}

// =============================================================================
extern "C" void kernel_launch(void* const* d_in, const int* in_sizes, int n_in,
                              void* d_out, int out_size) {
    const float* hs = (const float*)d_in[0];
    const float* w1 = (const float*)d_in[1];
    const float* b1 = (const float*)d_in[2];
    const float* w2 = (const float*)d_in[3];
    const float* b2 = (const float*)d_in[4];

    float* out = (float*)d_out;
    float* attn_out = out;                           // [B,S,E]
    float* wts = out + (size_t)NTOK * EMB;           // [B,H,S,S]

    cudaFuncSetAttribute(mma_gemm<0>,
                         cudaFuncAttributeMaxDynamicSharedMemorySize, GEMM_SMEM);
    cudaFuncSetAttribute(mma_gemm<1>,
                         cudaFuncAttributeMaxDynamicSharedMemorySize, GEMM_SMEM);
    cudaFuncSetAttribute(attn_kernel,
                         cudaFuncAttributeMaxDynamicSharedMemorySize, ATTN_SMEM);

    // side stream + events for graph-captured fork/join
    cudaStream_t s2;
    cudaStreamCreateWithFlags(&s2, cudaStreamNonBlocking);
    cudaEvent_t ev0, ev1, evw2, ev2, ev3;
    cudaEventCreateWithFlags(&ev0, cudaEventDisableTiming);
    cudaEventCreateWithFlags(&ev1, cudaEventDisableTiming);
    cudaEventCreateWithFlags(&evw2, cudaEventDisableTiming);
    cudaEventCreateWithFlags(&ev2, cudaEventDisableTiming);
    cudaEventCreateWithFlags(&ev3, cudaEventDisableTiming);

    // ---- fork 1: w1/w2 transposes then zero-fill (s2)  ||  hs split (main) --
    cudaEventRecord(ev0, 0);
    cudaStreamWaitEvent(s2, ev0, 0);
    transpose_split_kernel<0><<<dim3(96, 32), dim3(32, 8), 0, s2>>>(w1, 3 * EMB);
    cudaEventRecord(ev1, s2);                       // qkv gate: w1t ready
    transpose_split_kernel<1><<<dim3(32, 32), dim3(32, 8), 0, s2>>>(w2, EMB);
    cudaEventRecord(evw2, s2);                      // proj gate: w2t ready
    zero_fill_kernel<<<NB * NH * S_LEN, 128, 0, s2>>>(wts);  // runs under qkv

    split_kernel<<<(NTOK * EMB / 4) / 256, 256>>>(hs);
    cudaStreamWaitEvent(0, ev1, 0);

    // ---- main chain ----
    mma_gemm<0><<<dim3(24, 32), 128, GEMM_SMEM>>>(b1, nullptr);
    attn_kernel<<<dim3(32, 32), 128, ATTN_SMEM>>>(wts);

    // ---- fork 2: rescale (s2, DRAM-bound)  ||  proj (main, tensor-bound) ----
    cudaEventRecord(ev2, 0);
    cudaStreamWaitEvent(s2, ev2, 0);
    rescale_kernel<<<NB * NH * S_LEN, 128, 0, s2>>>(wts);
    cudaEventRecord(ev3, s2);

    cudaStreamWaitEvent(0, evw2, 0);
    mma_gemm<1><<<dim3(8, 32), 128, GEMM_SMEM>>>(b2, attn_out);
    cudaStreamWaitEvent(0, ev3, 0);                 // join
}

// round 14
// speedup vs baseline: 1.1022x; 1.0830x over previous
#include <cuda_runtime.h>
#include <cuda_bf16.h>
#include <float.h>
#include <math.h>
#include <stdint.h>

#define S_LEN 2048
#define EMB   1024
#define NH    16
#define HD    64
#define NB    2
#define NTOK  (NB * S_LEN)   // 4096

// ---------------- scratch (device globals: no allocation allowed) ------------
__device__ float g_linv[(size_t)NB * NH * S_LEN];     // per-row 1/l

__device__ __nv_bfloat16 g_qh[(size_t)NB * NH * S_LEN * HD];  // [B,H,S,D]
__device__ __nv_bfloat16 g_ql[(size_t)NB * NH * S_LEN * HD];
__device__ __nv_bfloat16 g_kh[(size_t)NB * NH * S_LEN * HD];
__device__ __nv_bfloat16 g_kl[(size_t)NB * NH * S_LEN * HD];
__device__ __nv_bfloat16 g_vh[(size_t)NB * NH * S_LEN * HD];
__device__ __nv_bfloat16 g_vl[(size_t)NB * NH * S_LEN * HD];
__device__ __nv_bfloat16 g_hs_hi[(size_t)NTOK * EMB];
__device__ __nv_bfloat16 g_hs_lo[(size_t)NTOK * EMB];
__device__ __nv_bfloat16 g_ao_hi[(size_t)NTOK * EMB];
__device__ __nv_bfloat16 g_ao_lo[(size_t)NTOK * EMB];
__device__ __nv_bfloat16 g_w1t_hi[(size_t)3 * EMB * EMB];  // [N=3072, K=1024]
__device__ __nv_bfloat16 g_w1t_lo[(size_t)3 * EMB * EMB];
__device__ __nv_bfloat16 g_w2t_hi[(size_t)EMB * EMB];      // [N=1024, K=1024]
__device__ __nv_bfloat16 g_w2t_lo[(size_t)EMB * EMB];

// ---------------- warp-MMA helpers ------------------------------------------
__device__ __forceinline__ uint32_t smem_u32(const void* p) {
    uint32_t a;
    asm("{ .reg .u64 t; cvta.to.shared.u64 t, %1; cvt.u32.u64 %0, t; }"
        : "=r"(a) : "l"(p));
    return a;
}
__device__ __forceinline__ void ldsm4(uint32_t& r0, uint32_t& r1,
                                      uint32_t& r2, uint32_t& r3, uint32_t addr) {
    asm volatile("ldmatrix.sync.aligned.m8n8.x4.shared.b16 {%0,%1,%2,%3}, [%4];"
                 : "=r"(r0), "=r"(r1), "=r"(r2), "=r"(r3) : "r"(addr));
}
__device__ __forceinline__ void ldsm4t(uint32_t& r0, uint32_t& r1,
                                       uint32_t& r2, uint32_t& r3, uint32_t addr) {
    asm volatile("ldmatrix.sync.aligned.m8n8.x4.trans.shared.b16 {%0,%1,%2,%3}, [%4];"
                 : "=r"(r0), "=r"(r1), "=r"(r2), "=r"(r3) : "r"(addr));
}
__device__ __forceinline__ void mma16816(float* c, const uint32_t* a,
                                         uint32_t b0, uint32_t b1) {
    asm volatile(
        "mma.sync.aligned.m16n8k16.row.col.f32.bf16.bf16.f32 "
        "{%0,%1,%2,%3}, {%4,%5,%6,%7}, {%8,%9}, {%0,%1,%2,%3};"
        : "+f"(c[0]), "+f"(c[1]), "+f"(c[2]), "+f"(c[3])
        : "r"(a[0]), "r"(a[1]), "r"(a[2]), "r"(a[3]), "r"(b0), "r"(b1));
}
__device__ __forceinline__ void cp16(uint32_t dst, const void* src) {
    asm volatile("cp.async.cg.shared.global [%0], [%1], 16;"
                 :: "r"(dst), "l"(src) : "memory");
}
#define CP_COMMIT() asm volatile("cp.async.commit_group;" ::: "memory")
template<int N>
__device__ __forceinline__ void cp_wait() {
    asm volatile("cp.async.wait_group %0;" :: "n"(N) : "memory");
}

// =============================================================================
// split-bf16 HMMA GEMM (round-10 measured-best variant, unchanged).
// =============================================================================
#define SP 40   // smem row pitch (bf16)
#define GEMM_SMEM (2 * 4 * 128 * SP * 2)   // 81920 B

template<int MODE>
__global__ __launch_bounds__(128, 2)
void mma_gemm(const float* __restrict__ bias, float* __restrict__ Cout) {
    extern __shared__ __nv_bfloat16 smg[];

    const int tid = threadIdx.x;
    const int wid = tid >> 5, lane = tid & 31;
    const int K = EMB;
    const int m0 = blockIdx.y * 128;
    const int n0 = blockIdx.x * 128;
    const int wm = wid & 1;
    const int wnw = wid >> 1;

    const __nv_bfloat16* __restrict__ gsrc[4] = {
        MODE ? g_ao_hi : g_hs_hi, MODE ? g_ao_lo : g_hs_lo,
        MODE ? g_w2t_hi : g_w1t_hi, MODE ? g_w2t_lo : g_w1t_lo};
    const int rb[4] = {m0, m0, n0, n0};

    const uint32_t sb = smem_u32(smg);
    const int BUF = 4 * 128 * SP;

    float acc[4][8][4];
#pragma unroll
    for (int i = 0; i < 4; i++)
#pragma unroll
        for (int j = 0; j < 8; j++)
#pragma unroll
            for (int k = 0; k < 4; k++) acc[i][j][k] = 0.f;

    const int grp = lane >> 3, lr = lane & 7;
    const int a_row = ((grp & 1) << 3) + lr;
    const int a_colh = (grp >> 1) << 3;
    const int b_row = ((grp >> 1) << 3) + lr;
    const int b_colh = (grp & 1) << 3;

    auto issue = [&](int t, int buf) {
#pragma unroll
        for (int arr = 0; arr < 4; arr++) {
#pragma unroll
            for (int r = 0; r < 4; r++) {
                int idx = r * 128 + tid;
                int row = idx >> 2, seg = idx & 3;
                cp16(sb + (buf * BUF + arr * 128 * SP + row * SP + seg * 8) * 2,
                     gsrc[arr] + (size_t)(rb[arr] + row) * K + t * 32 + seg * 8);
            }
        }
        CP_COMMIT();
    };

    issue(0, 0);

    const int nt = K / 32;
    for (int t = 0; t < nt; t++) {
        const int buf = t & 1;
        if (t + 1 < nt) { issue(t + 1, buf ^ 1); cp_wait<1>(); }
        else cp_wait<0>();
        __syncthreads();

        const uint32_t base = sb + buf * BUF * 2;
        const uint32_t aofs_hi = base;
        const uint32_t aofs_lo = base + 128 * SP * 2;
        const uint32_t bofs_hi = base + 2 * 128 * SP * 2;
        const uint32_t bofs_lo = base + 3 * 128 * SP * 2;

#pragma unroll
        for (int ks = 0; ks < 2; ks++) {
            const int k0 = ks * 16;
            uint32_t ah[4][4], al[4][4];
#pragma unroll
            for (int ma = 0; ma < 4; ma++) {
                int row = wm * 64 + ma * 16 + a_row;
                ldsm4(ah[ma][0], ah[ma][1], ah[ma][2], ah[ma][3],
                      aofs_hi + (row * SP + k0 + a_colh) * 2);
                ldsm4(al[ma][0], al[ma][1], al[ma][2], al[ma][3],
                      aofs_lo + (row * SP + k0 + a_colh) * 2);
            }
#pragma unroll
            for (int nb = 0; nb < 4; nb++) {
                int row = wnw * 64 + nb * 16 + b_row;
                int col = k0 + b_colh;
                uint32_t bh0, bh1, bh2, bh3, bl0, bl1, bl2, bl3;
                ldsm4(bh0, bh1, bh2, bh3, bofs_hi + (row * SP + col) * 2);
                ldsm4(bl0, bl1, bl2, bl3, bofs_lo + (row * SP + col) * 2);
#pragma unroll
                for (int ma = 0; ma < 4; ma++) {
                    mma16816(acc[ma][nb * 2 + 0], ah[ma], bh0, bh1);
                    mma16816(acc[ma][nb * 2 + 0], ah[ma], bl0, bl1);
                    mma16816(acc[ma][nb * 2 + 0], al[ma], bh0, bh1);
                    mma16816(acc[ma][nb * 2 + 1], ah[ma], bh2, bh3);
                    mma16816(acc[ma][nb * 2 + 1], ah[ma], bl2, bl3);
                    mma16816(acc[ma][nb * 2 + 1], al[ma], bh2, bh3);
                }
            }
        }
        __syncthreads();
    }

    // epilogue
#pragma unroll
    for (int ma = 0; ma < 4; ma++) {
#pragma unroll
        for (int na = 0; na < 8; na++) {
            float* c = acc[ma][na];
            const int gn = n0 + wnw * 64 + na * 8 + ((lane & 3) << 1);
            const float bx = bias[gn], by = bias[gn + 1];
            const int gr0 = m0 + wm * 64 + ma * 16 + (lane >> 2);
            if (MODE == 0) {
                const int which = gn >> 10;
                const int head  = (gn & 1023) >> 6;
                const int d     = gn & 63;
                __nv_bfloat16* dh = (which == 0) ? g_qh : ((which == 1) ? g_kh : g_vh);
                __nv_bfloat16* dl = (which == 0) ? g_ql : ((which == 1) ? g_kl : g_vl);
#pragma unroll
                for (int rr = 0; rr < 2; rr++) {
                    int gr = gr0 + rr * 8;
                    float x = c[rr * 2 + 0] + bx, y = c[rr * 2 + 1] + by;
                    __nv_bfloat162 h2 = __float22bfloat162_rn(make_float2(x, y));
                    __nv_bfloat162 l2 = __float22bfloat162_rn(
                        make_float2(x - __bfloat162float(h2.x),
                                    y - __bfloat162float(h2.y)));
                    size_t o = (((size_t)(gr >> 11) * NH + head) * S_LEN
                                + (gr & 2047)) * HD + d;
                    *(__nv_bfloat162*)&dh[o] = h2;
                    *(__nv_bfloat162*)&dl[o] = l2;
                }
            } else {
#pragma unroll
                for (int rr = 0; rr < 2; rr++) {
                    int gr = gr0 + rr * 8;
                    float2 o = {c[rr * 2 + 0] + bx, c[rr * 2 + 1] + by};
                    *(float2*)&Cout[(size_t)gr * EMB + gn] = o;
                }
            }
        }
    }
}

// =============================================================================
// HMMA causal attention, cp.async-prefetched K/V:
//   K(kt+1) issued during PV(kt); V(kt) issued during QK(kt).
// Groups complete in issue order -> wait_group<1> is exact.
// Everything else identical to round-10 (zero-fill in epilogue, etc).
// =============================================================================
#define AP 72
#define T64 (64 * AP)
#define ATTN_SMEM (8 * T64 * 2)              // 73728 B

__global__ __launch_bounds__(128, 3)
void attn_kernel(float* __restrict__ wout) {
    extern __shared__ __nv_bfloat16 sma[];
    __nv_bfloat16* const Qh = sma;
    __nv_bfloat16* const Ql = sma + T64;

    const int tid = threadIdx.x;
    const int lane = tid & 31, wid = tid >> 5;
    const int wm = wid & 1, wn = wid >> 1;
    const int qt = blockIdx.x, bh = blockIdx.y;
    const int q0 = qt * 64;
    const int b = bh >> 4, h = bh & 15;
    const float scale = 0.125f;

    const size_t hb = (size_t)bh * S_LEN * HD;
    const uint32_t sb = smem_u32(sma);
    const uint32_t uQh = sb, uQl = sb + T64 * 2;
    const uint32_t uKh = sb + 2 * T64 * 2, uKl = sb + 3 * T64 * 2;
    const uint32_t uVh = sb + 4 * T64 * 2, uVl = sb + 5 * T64 * 2;
    const uint32_t uPh = sb + 6 * T64 * 2, uPl = sb + 7 * T64 * 2;
    __nv_bfloat16* const Ph = sma + 6 * T64;
    __nv_bfloat16* const Pl = sma + 7 * T64;

    // Q tile (one-time, direct loads)
#pragma unroll
    for (int i = 0; i < 4; i++) {
        int idx = i * 128 + tid;
        int row = idx >> 3, seg = idx & 7;
        size_t go = hb + (size_t)(q0 + row) * HD + seg * 8;
        *(uint4*)&Qh[row * AP + seg * 8] = *(const uint4*)&g_qh[go];
        *(uint4*)&Ql[row * AP + seg * 8] = *(const uint4*)&g_ql[go];
    }

    auto issue_K = [&](int kt) {
#pragma unroll
        for (int i = 0; i < 4; i++) {
            int idx = i * 128 + tid;
            int row = idx >> 3, seg = idx & 7;
            size_t go = hb + (size_t)(kt * 64 + row) * HD + seg * 8;
            cp16(uKh + (row * AP + seg * 8) * 2, &g_kh[go]);
            cp16(uKl + (row * AP + seg * 8) * 2, &g_kl[go]);
        }
        CP_COMMIT();
    };
    auto issue_V = [&](int kt) {
#pragma unroll
        for (int i = 0; i < 4; i++) {
            int idx = i * 128 + tid;
            int row = idx >> 3, seg = idx & 7;
            size_t go = hb + (size_t)(kt * 64 + row) * HD + seg * 8;
            cp16(uVh + (row * AP + seg * 8) * 2, &g_vh[go]);
            cp16(uVl + (row * AP + seg * 8) * 2, &g_vl[go]);
        }
        CP_COMMIT();
    };

    const int grp = lane >> 3, lr = lane & 7;
    const int a_row = ((grp & 1) << 3) + lr;
    const int a_colh = (grp >> 1) << 3;
    const int b_row = ((grp >> 1) << 3) + lr;
    const int b_colh = (grp & 1) << 3;

    float oacc[2][4][4];
#pragma unroll
    for (int i = 0; i < 2; i++)
#pragma unroll
        for (int j = 0; j < 4; j++)
#pragma unroll
            for (int k = 0; k < 4; k++) oacc[i][j][k] = 0.f;
    float lacc[2][2] = {{0.f, 0.f}, {0.f, 0.f}};

    issue_K(0);   // prefetch first K tile

    for (int kt = 0; kt <= qt; kt++) {
        __syncthreads();            // prev PV done: V, P buffers free (also Q on kt=0)
        issue_V(kt);                // lands during QK phase
        cp_wait<1>();               // K(kt) complete (V still pending)
        __syncthreads();            // K visible to all warps

        // ---------- S = Q K^T ----------
        float sacc[2][4][4];
#pragma unroll
        for (int i = 0; i < 2; i++)
#pragma unroll
            for (int j = 0; j < 4; j++)
#pragma unroll
                for (int k = 0; k < 4; k++) sacc[i][j][k] = 0.f;

#pragma unroll
        for (int kc = 0; kc < 4; kc++) {
            const int k0 = kc * 16;
            uint32_t ah[2][4], al[2][4];
#pragma unroll
            for (int ma = 0; ma < 2; ma++) {
                int row = wm * 32 + ma * 16 + a_row;
                ldsm4(ah[ma][0], ah[ma][1], ah[ma][2], ah[ma][3],
                      uQh + (row * AP + k0 + a_colh) * 2);
                ldsm4(al[ma][0], al[ma][1], al[ma][2], al[ma][3],
                      uQl + (row * AP + k0 + a_colh) * 2);
            }
#pragma unroll
            for (int nb = 0; nb < 2; nb++) {
                int row = wn * 32 + nb * 16 + b_row;
                uint32_t bh0, bh1, bh2, bh3, bl0, bl1, bl2, bl3;
                ldsm4(bh0, bh1, bh2, bh3, uKh + (row * AP + k0 + b_colh) * 2);
                ldsm4(bl0, bl1, bl2, bl3, uKl + (row * AP + k0 + b_colh) * 2);
#pragma unroll
                for (int ma = 0; ma < 2; ma++) {
                    mma16816(sacc[ma][nb * 2 + 0], ah[ma], bh0, bh1);
                    mma16816(sacc[ma][nb * 2 + 0], ah[ma], bl0, bl1);
                    mma16816(sacc[ma][nb * 2 + 0], al[ma], bh0, bh1);
                    mma16816(sacc[ma][nb * 2 + 1], ah[ma], bh2, bh3);
                    mma16816(sacc[ma][nb * 2 + 1], ah[ma], bl2, bl3);
                    mma16816(sacc[ma][nb * 2 + 1], al[ma], bh2, bh3);
                }
            }
        }

        // ---------- exp, raw weights out, P -> smem hi/lo ----------
        const bool diag = (kt == qt);
#pragma unroll
        for (int ma = 0; ma < 2; ma++) {
#pragma unroll
            for (int na = 0; na < 4; na++) {
                float* c = sacc[ma][na];
                const int rl0 = wm * 32 + ma * 16 + (lane >> 2);
                const int cl = wn * 32 + na * 8 + ((lane & 3) << 1);
                const int gr0 = q0 + rl0, gc = kt * 64 + cl;
                float e00 = __expf(c[0] * scale);
                float e01 = __expf(c[1] * scale);
                float e10 = __expf(c[2] * scale);
                float e11 = __expf(c[3] * scale);
                if (diag) {
                    if (gc > gr0)     e00 = 0.f;
                    if (gc + 1 > gr0) e01 = 0.f;
                    if (gc > gr0 + 8)     e10 = 0.f;
                    if (gc + 1 > gr0 + 8) e11 = 0.f;
                }
                lacc[ma][0] += e00 + e01;
                lacc[ma][1] += e10 + e11;
                *(float2*)&wout[((size_t)bh * S_LEN + gr0) * S_LEN + gc] =
                    make_float2(e00, e01);
                *(float2*)&wout[((size_t)bh * S_LEN + gr0 + 8) * S_LEN + gc] =
                    make_float2(e10, e11);
                __nv_bfloat162 h0 = __float22bfloat162_rn(make_float2(e00, e01));
                __nv_bfloat162 h1 = __float22bfloat162_rn(make_float2(e10, e11));
                __nv_bfloat162 l0 = __float22bfloat162_rn(
                    make_float2(e00 - __bfloat162float(h0.x),
                                e01 - __bfloat162float(h0.y)));
                __nv_bfloat162 l1 = __float22bfloat162_rn(
                    make_float2(e10 - __bfloat162float(h1.x),
                                e11 - __bfloat162float(h1.y)));
                *(__nv_bfloat162*)&Ph[rl0 * AP + cl] = h0;
                *(__nv_bfloat162*)&Ph[(rl0 + 8) * AP + cl] = h1;
                *(__nv_bfloat162*)&Pl[rl0 * AP + cl] = l0;
                *(__nv_bfloat162*)&Pl[(rl0 + 8) * AP + cl] = l1;
            }
        }
        __syncthreads();            // P visible; K fully consumed

        if (kt < qt) { issue_K(kt + 1); cp_wait<1>(); }  // wait V(kt)
        else cp_wait<0>();
        __syncthreads();            // V visible

        // ---------- O += P V ----------
#pragma unroll
        for (int kc = 0; kc < 4; kc++) {
            const int k0 = kc * 16;
            uint32_t ph[2][4], pl[2][4];
#pragma unroll
            for (int ma = 0; ma < 2; ma++) {
                int row = wm * 32 + ma * 16 + a_row;
                ldsm4(ph[ma][0], ph[ma][1], ph[ma][2], ph[ma][3],
                      uPh + (row * AP + k0 + a_colh) * 2);
                ldsm4(pl[ma][0], pl[ma][1], pl[ma][2], pl[ma][3],
                      uPl + (row * AP + k0 + a_colh) * 2);
            }
#pragma unroll
            for (int ndl = 0; ndl < 2; ndl++) {
                int vrow = k0 + ((grp & 1) << 3) + lr;
                int vcol = wn * 32 + ndl * 16 + ((grp >> 1) << 3);
                uint32_t vh0, vh1, vh2, vh3, vl0, vl1, vl2, vl3;
                ldsm4t(vh0, vh1, vh2, vh3, uVh + (vrow * AP + vcol) * 2);
                ldsm4t(vl0, vl1, vl2, vl3, uVl + (vrow * AP + vcol) * 2);
#pragma unroll
                for (int ma = 0; ma < 2; ma++) {
                    mma16816(oacc[ma][ndl * 2 + 0], ph[ma], vh0, vh1);
                    mma16816(oacc[ma][ndl * 2 + 0], ph[ma], vl0, vl1);
                    mma16816(oacc[ma][ndl * 2 + 0], pl[ma], vh0, vh1);
                    mma16816(oacc[ma][ndl * 2 + 1], ph[ma], vh2, vh3);
                    mma16816(oacc[ma][ndl * 2 + 1], ph[ma], vl2, vl3);
                    mma16816(oacc[ma][ndl * 2 + 1], pl[ma], vh2, vh3);
                }
            }
        }
    }

    // zero-fill fully-masked upper region (d_out poisoned)
    {
        const int ce = (qt + 1) * 64;
        const int n4 = (S_LEN - ce) >> 2;
        const float4 z = {0.f, 0.f, 0.f, 0.f};
        for (int i = tid; i < 64 * n4; i += 128) {
            int r = i / n4, c = i - r * n4;
            *(float4*)&wout[((size_t)bh * S_LEN + q0 + r) * S_LEN + ce + c * 4] = z;
        }
    }

    // ---------- l reduction ----------
    __syncthreads();
    float* fs = (float*)sma;

#pragma unroll
    for (int ma = 0; ma < 2; ma++) {
#pragma unroll
        for (int half = 0; half < 2; half++) {
            float v = lacc[ma][half];
            v += __shfl_xor_sync(0xffffffffu, v, 1);
            v += __shfl_xor_sync(0xffffffffu, v, 2);
            if ((lane & 3) == 0)
                fs[wn * 64 + wm * 32 + ma * 16 + half * 8 + (lane >> 2)] = v;
        }
    }
    __syncthreads();
    if (tid < 64) {
        float inv = 1.f / (fs[tid] + fs[64 + tid]);
        fs[128 + tid] = inv;
        g_linv[(size_t)bh * S_LEN + q0 + tid] = inv;
    }
    __syncthreads();

    // ---------- normalized O -> g_ao hi/lo ----------
#pragma unroll
    for (int ma = 0; ma < 2; ma++)
#pragma unroll
        for (int nd = 0; nd < 4; nd++) {
            float* c = oacc[ma][nd];
            int rl0 = wm * 32 + ma * 16 + (lane >> 2);
            int d0 = wn * 32 + nd * 8 + ((lane & 3) << 1);
#pragma unroll
            for (int rr = 0; rr < 2; rr++) {
                int rl = rl0 + rr * 8;
                float inv = fs[128 + rl];
                float x = c[rr * 2 + 0] * inv, y = c[rr * 2 + 1] * inv;
                __nv_bfloat162 h2 = __float22bfloat162_rn(make_float2(x, y));
                __nv_bfloat162 l2 = __float22bfloat162_rn(
                    make_float2(x - __bfloat162float(h2.x),
                                y - __bfloat162float(h2.y)));
                size_t tok = (size_t)b * S_LEN + q0 + rl;
                *(__nv_bfloat162*)&g_ao_hi[tok * EMB + h * HD + d0] = h2;
                *(__nv_bfloat162*)&g_ao_lo[tok * EMB + h * HD + d0] = l2;
            }
        }
}

// =============================================================================
// fp32 hidden_states -> (hi, lo) bf16 split.
// =============================================================================
__global__ void split_kernel(const float* __restrict__ src) {
    const size_t i4 = (size_t)blockIdx.x * blockDim.x + threadIdx.x;
    float4 v = ((const float4*)src)[i4];
    float f[4] = {v.x, v.y, v.z, v.w};
    __nv_bfloat16 h[4], l[4];
#pragma unroll
    for (int j = 0; j < 4; j++) {
        h[j] = __float2bfloat16(f[j]);
        l[j] = __float2bfloat16(f[j] - __bfloat162float(h[j]));
    }
    *(uint2*)&g_hs_hi[i4 * 4] = *(uint2*)h;
    *(uint2*)&g_hs_lo[i4 * 4] = *(uint2*)l;
}

// =============================================================================
// W [K,N] fp32 -> Wt_{hi,lo} [N,K] bf16.
// =============================================================================
template<int WHICH>
__global__ void transpose_split_kernel(const float* __restrict__ W, int N) {
    __shared__ float t[32][33];
    __nv_bfloat16* hi = WHICH ? g_w2t_hi : g_w1t_hi;
    __nv_bfloat16* lo = WHICH ? g_w2t_lo : g_w1t_lo;
    const int K = EMB;
    const int nx = blockIdx.x * 32, ky = blockIdx.y * 32;
    const int tx = threadIdx.x, ty = threadIdx.y;
#pragma unroll
    for (int i = 0; i < 4; i++)
        t[ty + i * 8][tx] = W[(size_t)(ky + ty + i * 8) * N + nx + tx];
    __syncthreads();
#pragma unroll
    for (int i = 0; i < 4; i++) {
        float v = t[tx][ty + i * 8];
        __nv_bfloat16 hh = __float2bfloat16(v);
        __nv_bfloat16 ll = __float2bfloat16(v - __bfloat162float(hh));
        size_t o = (size_t)(nx + ty + i * 8) * K + ky + tx;
        hi[o] = hh;
        lo[o] = ll;
    }
}

// =============================================================================
__global__ void rescale_kernel(float* __restrict__ wout) {
    const int row = blockIdx.x;
    const int s = row & (S_LEN - 1);
    const float inv = g_linv[row];
    float4* p = (float4*)(wout + (size_t)row * S_LEN);
    const int n4 = (s + 4) >> 2;           // overshoot hits zeros (attn ran first)
    for (int i = threadIdx.x; i < n4; i += blockDim.x) {
        float4 v = p[i];
        v.x *= inv; v.y *= inv; v.z *= inv; v.w *= inv;
        p[i] = v;
    }
}

// =============================================================================
extern "C" void kernel_launch(void* const* d_in, const int* in_sizes, int n_in,
                              void* d_out, int out_size) {
    const float* hs = (const float*)d_in[0];
    const float* w1 = (const float*)d_in[1];
    const float* b1 = (const float*)d_in[2];
    const float* w2 = (const float*)d_in[3];
    const float* b2 = (const float*)d_in[4];

    float* out = (float*)d_out;
    float* attn_out = out;                           // [B,S,E]
    float* wts = out + (size_t)NTOK * EMB;           // [B,H,S,S]

    cudaFuncSetAttribute(mma_gemm<0>,
                         cudaFuncAttributeMaxDynamicSharedMemorySize, GEMM_SMEM);
    cudaFuncSetAttribute(mma_gemm<1>,
                         cudaFuncAttributeMaxDynamicSharedMemorySize, GEMM_SMEM);
    cudaFuncSetAttribute(attn_kernel,
                         cudaFuncAttributeMaxDynamicSharedMemorySize, ATTN_SMEM);

    // side stream + events for graph-captured fork/join
    cudaStream_t s2;
    cudaStreamCreateWithFlags(&s2, cudaStreamNonBlocking);
    cudaEvent_t ev0, ev1, evw2, ev2, ev3;
    cudaEventCreateWithFlags(&ev0, cudaEventDisableTiming);
    cudaEventCreateWithFlags(&ev1, cudaEventDisableTiming);
    cudaEventCreateWithFlags(&evw2, cudaEventDisableTiming);
    cudaEventCreateWithFlags(&ev2, cudaEventDisableTiming);
    cudaEventCreateWithFlags(&ev3, cudaEventDisableTiming);

    // ---- fork 1: w1/w2 transposes (s2)  ||  hs split (main) ----
    cudaEventRecord(ev0, 0);
    cudaStreamWaitEvent(s2, ev0, 0);
    transpose_split_kernel<0><<<dim3(96, 32), dim3(32, 8), 0, s2>>>(w1, 3 * EMB);
    cudaEventRecord(ev1, s2);                       // qkv gate: w1t ready
    transpose_split_kernel<1><<<dim3(32, 32), dim3(32, 8), 0, s2>>>(w2, EMB);
    cudaEventRecord(evw2, s2);                      // proj gate: w2t ready

    split_kernel<<<(NTOK * EMB / 4) / 256, 256>>>(hs);
    cudaStreamWaitEvent(0, ev1, 0);

    // ---- main chain ----
    mma_gemm<0><<<dim3(24, 32), 128, GEMM_SMEM>>>(b1, nullptr);
    attn_kernel<<<dim3(32, 32), 128, ATTN_SMEM>>>(wts);

    // ---- fork 2: rescale (s2, DRAM-bound)  ||  proj (main, tensor-bound) ----
    cudaEventRecord(ev2, 0);
    cudaStreamWaitEvent(s2, ev2, 0);
    rescale_kernel<<<NB * NH * S_LEN, 128, 0, s2>>>(wts);
    cudaEventRecord(ev3, s2);

    cudaStreamWaitEvent(0, evw2, 0);
    mma_gemm<1><<<dim3(8, 32), 128, GEMM_SMEM>>>(b2, attn_out);
    cudaStreamWaitEvent(0, ev3, 0);                 // join
}

// round 15
// speedup vs baseline: 1.1359x; 1.0306x over previous
#include <cuda_runtime.h>
#include <cuda_bf16.h>
#include <float.h>
#include <math.h>
#include <stdint.h>

#define S_LEN 2048
#define EMB   1024
#define NH    16
#define HD    64
#define NB    2
#define NTOK  (NB * S_LEN)   // 4096

// ---------------- scratch (device globals: no allocation allowed) ------------
__device__ float g_linv[(size_t)NB * NH * S_LEN];     // per-row 1/l

__device__ __nv_bfloat16 g_qh[(size_t)NB * NH * S_LEN * HD];  // [B,H,S,D]
__device__ __nv_bfloat16 g_ql[(size_t)NB * NH * S_LEN * HD];
__device__ __nv_bfloat16 g_kh[(size_t)NB * NH * S_LEN * HD];
__device__ __nv_bfloat16 g_kl[(size_t)NB * NH * S_LEN * HD];
__device__ __nv_bfloat16 g_vh[(size_t)NB * NH * S_LEN * HD];
__device__ __nv_bfloat16 g_vl[(size_t)NB * NH * S_LEN * HD];
__device__ __nv_bfloat16 g_hs_hi[(size_t)NTOK * EMB];
__device__ __nv_bfloat16 g_hs_lo[(size_t)NTOK * EMB];
__device__ __nv_bfloat16 g_ao_hi[(size_t)NTOK * EMB];
__device__ __nv_bfloat16 g_ao_lo[(size_t)NTOK * EMB];
__device__ __nv_bfloat16 g_w1t_hi[(size_t)3 * EMB * EMB];  // [N=3072, K=1024]
__device__ __nv_bfloat16 g_w1t_lo[(size_t)3 * EMB * EMB];
__device__ __nv_bfloat16 g_w2t_hi[(size_t)EMB * EMB];      // [N=1024, K=1024]
__device__ __nv_bfloat16 g_w2t_lo[(size_t)EMB * EMB];

// ---------------- warp-MMA helpers ------------------------------------------
__device__ __forceinline__ uint32_t smem_u32(const void* p) {
    uint32_t a;
    asm("{ .reg .u64 t; cvta.to.shared.u64 t, %1; cvt.u32.u64 %0, t; }"
        : "=r"(a) : "l"(p));
    return a;
}
__device__ __forceinline__ void ldsm4(uint32_t& r0, uint32_t& r1,
                                      uint32_t& r2, uint32_t& r3, uint32_t addr) {
    asm volatile("ldmatrix.sync.aligned.m8n8.x4.shared.b16 {%0,%1,%2,%3}, [%4];"
                 : "=r"(r0), "=r"(r1), "=r"(r2), "=r"(r3) : "r"(addr));
}
__device__ __forceinline__ void ldsm4t(uint32_t& r0, uint32_t& r1,
                                       uint32_t& r2, uint32_t& r3, uint32_t addr) {
    asm volatile("ldmatrix.sync.aligned.m8n8.x4.trans.shared.b16 {%0,%1,%2,%3}, [%4];"
                 : "=r"(r0), "=r"(r1), "=r"(r2), "=r"(r3) : "r"(addr));
}
__device__ __forceinline__ void mma16816(float* c, const uint32_t* a,
                                         uint32_t b0, uint32_t b1) {
    asm volatile(
        "mma.sync.aligned.m16n8k16.row.col.f32.bf16.bf16.f32 "
        "{%0,%1,%2,%3}, {%4,%5,%6,%7}, {%8,%9}, {%0,%1,%2,%3};"
        : "+f"(c[0]), "+f"(c[1]), "+f"(c[2]), "+f"(c[3])
        : "r"(a[0]), "r"(a[1]), "r"(a[2]), "r"(a[3]), "r"(b0), "r"(b1));
}
__device__ __forceinline__ void cp16(uint32_t dst, const void* src) {
    asm volatile("cp.async.cg.shared.global [%0], [%1], 16;"
                 :: "r"(dst), "l"(src) : "memory");
}
#define CP_COMMIT() asm volatile("cp.async.commit_group;" ::: "memory")
template<int N>
__device__ __forceinline__ void cp_wait() {
    asm volatile("cp.async.wait_group %0;" :: "n"(N) : "memory");
}

// =============================================================================
// split-bf16 HMMA GEMM (round-10 loop), with m-base offset for half launches.
// =============================================================================
#define SP 40   // smem row pitch (bf16)
#define GEMM_SMEM (2 * 4 * 128 * SP * 2)   // 81920 B

template<int MODE>
__global__ __launch_bounds__(128, 2)
void mma_gemm(const float* __restrict__ bias, float* __restrict__ Cout,
              int mbase) {
    extern __shared__ __nv_bfloat16 smg[];

    const int tid = threadIdx.x;
    const int wid = tid >> 5, lane = tid & 31;
    const int K = EMB;
    const int m0 = mbase + blockIdx.y * 128;
    const int n0 = blockIdx.x * 128;
    const int wm = wid & 1;
    const int wnw = wid >> 1;

    const __nv_bfloat16* __restrict__ gsrc[4] = {
        MODE ? g_ao_hi : g_hs_hi, MODE ? g_ao_lo : g_hs_lo,
        MODE ? g_w2t_hi : g_w1t_hi, MODE ? g_w2t_lo : g_w1t_lo};
    const int rb[4] = {m0, m0, n0, n0};

    const uint32_t sb = smem_u32(smg);
    const int BUF = 4 * 128 * SP;

    float acc[4][8][4];
#pragma unroll
    for (int i = 0; i < 4; i++)
#pragma unroll
        for (int j = 0; j < 8; j++)
#pragma unroll
            for (int k = 0; k < 4; k++) acc[i][j][k] = 0.f;

    const int grp = lane >> 3, lr = lane & 7;
    const int a_row = ((grp & 1) << 3) + lr;
    const int a_colh = (grp >> 1) << 3;
    const int b_row = ((grp >> 1) << 3) + lr;
    const int b_colh = (grp & 1) << 3;

    auto issue = [&](int t, int buf) {
#pragma unroll
        for (int arr = 0; arr < 4; arr++) {
#pragma unroll
            for (int r = 0; r < 4; r++) {
                int idx = r * 128 + tid;
                int row = idx >> 2, seg = idx & 3;
                cp16(sb + (buf * BUF + arr * 128 * SP + row * SP + seg * 8) * 2,
                     gsrc[arr] + (size_t)(rb[arr] + row) * K + t * 32 + seg * 8);
            }
        }
        CP_COMMIT();
    };

    issue(0, 0);

    const int nt = K / 32;
    for (int t = 0; t < nt; t++) {
        const int buf = t & 1;
        if (t + 1 < nt) { issue(t + 1, buf ^ 1); cp_wait<1>(); }
        else cp_wait<0>();
        __syncthreads();

        const uint32_t base = sb + buf * BUF * 2;
        const uint32_t aofs_hi = base;
        const uint32_t aofs_lo = base + 128 * SP * 2;
        const uint32_t bofs_hi = base + 2 * 128 * SP * 2;
        const uint32_t bofs_lo = base + 3 * 128 * SP * 2;

#pragma unroll
        for (int ks = 0; ks < 2; ks++) {
            const int k0 = ks * 16;
            uint32_t ah[4][4], al[4][4];
#pragma unroll
            for (int ma = 0; ma < 4; ma++) {
                int row = wm * 64 + ma * 16 + a_row;
                ldsm4(ah[ma][0], ah[ma][1], ah[ma][2], ah[ma][3],
                      aofs_hi + (row * SP + k0 + a_colh) * 2);
                ldsm4(al[ma][0], al[ma][1], al[ma][2], al[ma][3],
                      aofs_lo + (row * SP + k0 + a_colh) * 2);
            }
#pragma unroll
            for (int nb = 0; nb < 4; nb++) {
                int row = wnw * 64 + nb * 16 + b_row;
                int col = k0 + b_colh;
                uint32_t bh0, bh1, bh2, bh3, bl0, bl1, bl2, bl3;
                ldsm4(bh0, bh1, bh2, bh3, bofs_hi + (row * SP + col) * 2);
                ldsm4(bl0, bl1, bl2, bl3, bofs_lo + (row * SP + col) * 2);
#pragma unroll
                for (int ma = 0; ma < 4; ma++) {
                    mma16816(acc[ma][nb * 2 + 0], ah[ma], bh0, bh1);
                    mma16816(acc[ma][nb * 2 + 0], ah[ma], bl0, bl1);
                    mma16816(acc[ma][nb * 2 + 0], al[ma], bh0, bh1);
                    mma16816(acc[ma][nb * 2 + 1], ah[ma], bh2, bh3);
                    mma16816(acc[ma][nb * 2 + 1], ah[ma], bl2, bl3);
                    mma16816(acc[ma][nb * 2 + 1], al[ma], bh2, bh3);
                }
            }
        }
        __syncthreads();
    }

    // epilogue
#pragma unroll
    for (int ma = 0; ma < 4; ma++) {
#pragma unroll
        for (int na = 0; na < 8; na++) {
            float* c = acc[ma][na];
            const int gn = n0 + wnw * 64 + na * 8 + ((lane & 3) << 1);
            const float bx = bias[gn], by = bias[gn + 1];
            const int gr0 = m0 + wm * 64 + ma * 16 + (lane >> 2);
            if (MODE == 0) {
                const int which = gn >> 10;
                const int head  = (gn & 1023) >> 6;
                const int d     = gn & 63;
                __nv_bfloat16* dh = (which == 0) ? g_qh : ((which == 1) ? g_kh : g_vh);
                __nv_bfloat16* dl = (which == 0) ? g_ql : ((which == 1) ? g_kl : g_vl);
#pragma unroll
                for (int rr = 0; rr < 2; rr++) {
                    int gr = gr0 + rr * 8;
                    float x = c[rr * 2 + 0] + bx, y = c[rr * 2 + 1] + by;
                    __nv_bfloat162 h2 = __float22bfloat162_rn(make_float2(x, y));
                    __nv_bfloat162 l2 = __float22bfloat162_rn(
                        make_float2(x - __bfloat162float(h2.x),
                                    y - __bfloat162float(h2.y)));
                    size_t o = (((size_t)(gr >> 11) * NH + head) * S_LEN
                                + (gr & 2047)) * HD + d;
                    *(__nv_bfloat162*)&dh[o] = h2;
                    *(__nv_bfloat162*)&dl[o] = l2;
                }
            } else {
#pragma unroll
                for (int rr = 0; rr < 2; rr++) {
                    int gr = gr0 + rr * 8;
                    float2 o = {c[rr * 2 + 0] + bx, c[rr * 2 + 1] + by};
                    *(float2*)&Cout[(size_t)gr * EMB + gn] = o;
                }
            }
        }
    }
}

// =============================================================================
// HMMA causal attention with cp.async K/V prefetch (round-14 version),
// plus bh-base offset for per-batch half launches.
// =============================================================================
#define AP 72
#define T64 (64 * AP)
#define ATTN_SMEM (8 * T64 * 2)              // 73728 B

__global__ __launch_bounds__(128, 3)
void attn_kernel(float* __restrict__ wout, int bhbase) {
    extern __shared__ __nv_bfloat16 sma[];
    __nv_bfloat16* const Qh = sma;
    __nv_bfloat16* const Ql = sma + T64;

    const int tid = threadIdx.x;
    const int lane = tid & 31, wid = tid >> 5;
    const int wm = wid & 1, wn = wid >> 1;
    const int qt = blockIdx.x;
    const int bh = bhbase + blockIdx.y;
    const int q0 = qt * 64;
    const int b = bh >> 4, h = bh & 15;
    const float scale = 0.125f;

    const size_t hb = (size_t)bh * S_LEN * HD;
    const uint32_t sb = smem_u32(sma);
    const uint32_t uQh = sb, uQl = sb + T64 * 2;
    const uint32_t uKh = sb + 2 * T64 * 2, uKl = sb + 3 * T64 * 2;
    const uint32_t uVh = sb + 4 * T64 * 2, uVl = sb + 5 * T64 * 2;
    const uint32_t uPh = sb + 6 * T64 * 2, uPl = sb + 7 * T64 * 2;
    __nv_bfloat16* const Ph = sma + 6 * T64;
    __nv_bfloat16* const Pl = sma + 7 * T64;

    // Q tile (one-time, direct loads)
#pragma unroll
    for (int i = 0; i < 4; i++) {
        int idx = i * 128 + tid;
        int row = idx >> 3, seg = idx & 7;
        size_t go = hb + (size_t)(q0 + row) * HD + seg * 8;
        *(uint4*)&Qh[row * AP + seg * 8] = *(const uint4*)&g_qh[go];
        *(uint4*)&Ql[row * AP + seg * 8] = *(const uint4*)&g_ql[go];
    }

    auto issue_K = [&](int kt) {
#pragma unroll
        for (int i = 0; i < 4; i++) {
            int idx = i * 128 + tid;
            int row = idx >> 3, seg = idx & 7;
            size_t go = hb + (size_t)(kt * 64 + row) * HD + seg * 8;
            cp16(uKh + (row * AP + seg * 8) * 2, &g_kh[go]);
            cp16(uKl + (row * AP + seg * 8) * 2, &g_kl[go]);
        }
        CP_COMMIT();
    };
    auto issue_V = [&](int kt) {
#pragma unroll
        for (int i = 0; i < 4; i++) {
            int idx = i * 128 + tid;
            int row = idx >> 3, seg = idx & 7;
            size_t go = hb + (size_t)(kt * 64 + row) * HD + seg * 8;
            cp16(uVh + (row * AP + seg * 8) * 2, &g_vh[go]);
            cp16(uVl + (row * AP + seg * 8) * 2, &g_vl[go]);
        }
        CP_COMMIT();
    };

    const int grp = lane >> 3, lr = lane & 7;
    const int a_row = ((grp & 1) << 3) + lr;
    const int a_colh = (grp >> 1) << 3;
    const int b_row = ((grp >> 1) << 3) + lr;
    const int b_colh = (grp & 1) << 3;

    float oacc[2][4][4];
#pragma unroll
    for (int i = 0; i < 2; i++)
#pragma unroll
        for (int j = 0; j < 4; j++)
#pragma unroll
            for (int k = 0; k < 4; k++) oacc[i][j][k] = 0.f;
    float lacc[2][2] = {{0.f, 0.f}, {0.f, 0.f}};

    issue_K(0);

    for (int kt = 0; kt <= qt; kt++) {
        __syncthreads();            // prev PV done: V, P buffers free (Q on kt=0)
        issue_V(kt);                // lands during QK phase
        cp_wait<1>();               // K(kt) complete
        __syncthreads();

        // ---------- S = Q K^T ----------
        float sacc[2][4][4];
#pragma unroll
        for (int i = 0; i < 2; i++)
#pragma unroll
            for (int j = 0; j < 4; j++)
#pragma unroll
                for (int k = 0; k < 4; k++) sacc[i][j][k] = 0.f;

#pragma unroll
        for (int kc = 0; kc < 4; kc++) {
            const int k0 = kc * 16;
            uint32_t ah[2][4], al[2][4];
#pragma unroll
            for (int ma = 0; ma < 2; ma++) {
                int row = wm * 32 + ma * 16 + a_row;
                ldsm4(ah[ma][0], ah[ma][1], ah[ma][2], ah[ma][3],
                      uQh + (row * AP + k0 + a_colh) * 2);
                ldsm4(al[ma][0], al[ma][1], al[ma][2], al[ma][3],
                      uQl + (row * AP + k0 + a_colh) * 2);
            }
#pragma unroll
            for (int nb = 0; nb < 2; nb++) {
                int row = wn * 32 + nb * 16 + b_row;
                uint32_t bh0, bh1, bh2, bh3, bl0, bl1, bl2, bl3;
                ldsm4(bh0, bh1, bh2, bh3, uKh + (row * AP + k0 + b_colh) * 2);
                ldsm4(bl0, bl1, bl2, bl3, uKl + (row * AP + k0 + b_colh) * 2);
#pragma unroll
                for (int ma = 0; ma < 2; ma++) {
                    mma16816(sacc[ma][nb * 2 + 0], ah[ma], bh0, bh1);
                    mma16816(sacc[ma][nb * 2 + 0], ah[ma], bl0, bl1);
                    mma16816(sacc[ma][nb * 2 + 0], al[ma], bh0, bh1);
                    mma16816(sacc[ma][nb * 2 + 1], ah[ma], bh2, bh3);
                    mma16816(sacc[ma][nb * 2 + 1], ah[ma], bl2, bl3);
                    mma16816(sacc[ma][nb * 2 + 1], al[ma], bh2, bh3);
                }
            }
        }

        // ---------- exp, raw weights out, P -> smem hi/lo ----------
        const bool diag = (kt == qt);
#pragma unroll
        for (int ma = 0; ma < 2; ma++) {
#pragma unroll
            for (int na = 0; na < 4; na++) {
                float* c = sacc[ma][na];
                const int rl0 = wm * 32 + ma * 16 + (lane >> 2);
                const int cl = wn * 32 + na * 8 + ((lane & 3) << 1);
                const int gr0 = q0 + rl0, gc = kt * 64 + cl;
                float e00 = __expf(c[0] * scale);
                float e01 = __expf(c[1] * scale);
                float e10 = __expf(c[2] * scale);
                float e11 = __expf(c[3] * scale);
                if (diag) {
                    if (gc > gr0)     e00 = 0.f;
                    if (gc + 1 > gr0) e01 = 0.f;
                    if (gc > gr0 + 8)     e10 = 0.f;
                    if (gc + 1 > gr0 + 8) e11 = 0.f;
                }
                lacc[ma][0] += e00 + e01;
                lacc[ma][1] += e10 + e11;
                *(float2*)&wout[((size_t)bh * S_LEN + gr0) * S_LEN + gc] =
                    make_float2(e00, e01);
                *(float2*)&wout[((size_t)bh * S_LEN + gr0 + 8) * S_LEN + gc] =
                    make_float2(e10, e11);
                __nv_bfloat162 h0 = __float22bfloat162_rn(make_float2(e00, e01));
                __nv_bfloat162 h1 = __float22bfloat162_rn(make_float2(e10, e11));
                __nv_bfloat162 l0 = __float22bfloat162_rn(
                    make_float2(e00 - __bfloat162float(h0.x),
                                e01 - __bfloat162float(h0.y)));
                __nv_bfloat162 l1 = __float22bfloat162_rn(
                    make_float2(e10 - __bfloat162float(h1.x),
                                e11 - __bfloat162float(h1.y)));
                *(__nv_bfloat162*)&Ph[rl0 * AP + cl] = h0;
                *(__nv_bfloat162*)&Ph[(rl0 + 8) * AP + cl] = h1;
                *(__nv_bfloat162*)&Pl[rl0 * AP + cl] = l0;
                *(__nv_bfloat162*)&Pl[(rl0 + 8) * AP + cl] = l1;
            }
        }
        __syncthreads();            // P visible; K fully consumed

        if (kt < qt) { issue_K(kt + 1); cp_wait<1>(); }
        else cp_wait<0>();
        __syncthreads();            // V visible

        // ---------- O += P V ----------
#pragma unroll
        for (int kc = 0; kc < 4; kc++) {
            const int k0 = kc * 16;
            uint32_t ph[2][4], pl[2][4];
#pragma unroll
            for (int ma = 0; ma < 2; ma++) {
                int row = wm * 32 + ma * 16 + a_row;
                ldsm4(ph[ma][0], ph[ma][1], ph[ma][2], ph[ma][3],
                      uPh + (row * AP + k0 + a_colh) * 2);
                ldsm4(pl[ma][0], pl[ma][1], pl[ma][2], pl[ma][3],
                      uPl + (row * AP + k0 + a_colh) * 2);
            }
#pragma unroll
            for (int ndl = 0; ndl < 2; ndl++) {
                int vrow = k0 + ((grp & 1) << 3) + lr;
                int vcol = wn * 32 + ndl * 16 + ((grp >> 1) << 3);
                uint32_t vh0, vh1, vh2, vh3, vl0, vl1, vl2, vl3;
                ldsm4t(vh0, vh1, vh2, vh3, uVh + (vrow * AP + vcol) * 2);
                ldsm4t(vl0, vl1, vl2, vl3, uVl + (vrow * AP + vcol) * 2);
#pragma unroll
                for (int ma = 0; ma < 2; ma++) {
                    mma16816(oacc[ma][ndl * 2 + 0], ph[ma], vh0, vh1);
                    mma16816(oacc[ma][ndl * 2 + 0], ph[ma], vl0, vl1);
                    mma16816(oacc[ma][ndl * 2 + 0], pl[ma], vh0, vh1);
                    mma16816(oacc[ma][ndl * 2 + 1], ph[ma], vh2, vh3);
                    mma16816(oacc[ma][ndl * 2 + 1], ph[ma], vl2, vl3);
                    mma16816(oacc[ma][ndl * 2 + 1], pl[ma], vh2, vh3);
                }
            }
        }
    }

    // zero-fill fully-masked upper region (d_out poisoned)
    {
        const int ce = (qt + 1) * 64;
        const int n4 = (S_LEN - ce) >> 2;
        const float4 z = {0.f, 0.f, 0.f, 0.f};
        for (int i = tid; i < 64 * n4; i += 128) {
            int r = i / n4, c = i - r * n4;
            *(float4*)&wout[((size_t)bh * S_LEN + q0 + r) * S_LEN + ce + c * 4] = z;
        }
    }

    // ---------- l reduction ----------
    __syncthreads();
    float* fs = (float*)sma;

#pragma unroll
    for (int ma = 0; ma < 2; ma++) {
#pragma unroll
        for (int half = 0; half < 2; half++) {
            float v = lacc[ma][half];
            v += __shfl_xor_sync(0xffffffffu, v, 1);
            v += __shfl_xor_sync(0xffffffffu, v, 2);
            if ((lane & 3) == 0)
                fs[wn * 64 + wm * 32 + ma * 16 + half * 8 + (lane >> 2)] = v;
        }
    }
    __syncthreads();
    if (tid < 64) {
        float inv = 1.f / (fs[tid] + fs[64 + tid]);
        fs[128 + tid] = inv;
        g_linv[(size_t)bh * S_LEN + q0 + tid] = inv;
    }
    __syncthreads();

    // ---------- normalized O -> g_ao hi/lo ----------
#pragma unroll
    for (int ma = 0; ma < 2; ma++)
#pragma unroll
        for (int nd = 0; nd < 4; nd++) {
            float* c = oacc[ma][nd];
            int rl0 = wm * 32 + ma * 16 + (lane >> 2);
            int d0 = wn * 32 + nd * 8 + ((lane & 3) << 1);
#pragma unroll
            for (int rr = 0; rr < 2; rr++) {
                int rl = rl0 + rr * 8;
                float inv = fs[128 + rl];
                float x = c[rr * 2 + 0] * inv, y = c[rr * 2 + 1] * inv;
                __nv_bfloat162 h2 = __float22bfloat162_rn(make_float2(x, y));
                __nv_bfloat162 l2 = __float22bfloat162_rn(
                    make_float2(x - __bfloat162float(h2.x),
                                y - __bfloat162float(h2.y)));
                size_t tok = (size_t)b * S_LEN + q0 + rl;
                *(__nv_bfloat162*)&g_ao_hi[tok * EMB + h * HD + d0] = h2;
                *(__nv_bfloat162*)&g_ao_lo[tok * EMB + h * HD + d0] = l2;
            }
        }
}

// =============================================================================
// fp32 hidden_states -> (hi, lo) bf16 split.
// =============================================================================
__global__ void split_kernel(const float* __restrict__ src) {
    const size_t i4 = (size_t)blockIdx.x * blockDim.x + threadIdx.x;
    float4 v = ((const float4*)src)[i4];
    float f[4] = {v.x, v.y, v.z, v.w};
    __nv_bfloat16 h[4], l[4];
#pragma unroll
    for (int j = 0; j < 4; j++) {
        h[j] = __float2bfloat16(f[j]);
        l[j] = __float2bfloat16(f[j] - __bfloat162float(h[j]));
    }
    *(uint2*)&g_hs_hi[i4 * 4] = *(uint2*)h;
    *(uint2*)&g_hs_lo[i4 * 4] = *(uint2*)l;
}

// =============================================================================
// W [K,N] fp32 -> Wt_{hi,lo} [N,K] bf16.
// =============================================================================
template<int WHICH>
__global__ void transpose_split_kernel(const float* __restrict__ W, int N) {
    __shared__ float t[32][33];
    __nv_bfloat16* hi = WHICH ? g_w2t_hi : g_w1t_hi;
    __nv_bfloat16* lo = WHICH ? g_w2t_lo : g_w1t_lo;
    const int K = EMB;
    const int nx = blockIdx.x * 32, ky = blockIdx.y * 32;
    const int tx = threadIdx.x, ty = threadIdx.y;
#pragma unroll
    for (int i = 0; i < 4; i++)
        t[ty + i * 8][tx] = W[(size_t)(ky + ty + i * 8) * N + nx + tx];
    __syncthreads();
#pragma unroll
    for (int i = 0; i < 4; i++) {
        float v = t[tx][ty + i * 8];
        __nv_bfloat16 hh = __float2bfloat16(v);
        __nv_bfloat16 ll = __float2bfloat16(v - __bfloat162float(hh));
        size_t o = (size_t)(nx + ty + i * 8) * K + ky + tx;
        hi[o] = hh;
        lo[o] = ll;
    }
}

// =============================================================================
__global__ void rescale_kernel(float* __restrict__ wout, int rowbase) {
    const int row = rowbase + blockIdx.x;
    const int s = row & (S_LEN - 1);
    const float inv = g_linv[row];
    float4* p = (float4*)(wout + (size_t)row * S_LEN);
    const int n4 = (s + 4) >> 2;           // overshoot hits zeros (attn ran first)
    for (int i = threadIdx.x; i < n4; i += blockDim.x) {
        float4 v = p[i];
        v.x *= inv; v.y *= inv; v.z *= inv; v.w *= inv;
        p[i] = v;
    }
}

// =============================================================================
extern "C" void kernel_launch(void* const* d_in, const int* in_sizes, int n_in,
                              void* d_out, int out_size) {
    const float* hs = (const float*)d_in[0];
    const float* w1 = (const float*)d_in[1];
    const float* b1 = (const float*)d_in[2];
    const float* w2 = (const float*)d_in[3];
    const float* b2 = (const float*)d_in[4];

    float* out = (float*)d_out;
    float* attn_out = out;                           // [B,S,E]
    float* wts = out + (size_t)NTOK * EMB;           // [B,H,S,S]

    cudaFuncSetAttribute(mma_gemm<0>,
                         cudaFuncAttributeMaxDynamicSharedMemorySize, GEMM_SMEM);
    cudaFuncSetAttribute(mma_gemm<1>,
                         cudaFuncAttributeMaxDynamicSharedMemorySize, GEMM_SMEM);
    cudaFuncSetAttribute(attn_kernel,
                         cudaFuncAttributeMaxDynamicSharedMemorySize, ATTN_SMEM);

    // side stream + events for graph-captured fork/join
    cudaStream_t s2;
    cudaStreamCreateWithFlags(&s2, cudaStreamNonBlocking);
    cudaEvent_t ev0, ev1, evw2, ev_q1, ev_a0, ev_a1, ev_r;
    cudaEventCreateWithFlags(&ev0, cudaEventDisableTiming);
    cudaEventCreateWithFlags(&ev1, cudaEventDisableTiming);
    cudaEventCreateWithFlags(&evw2, cudaEventDisableTiming);
    cudaEventCreateWithFlags(&ev_q1, cudaEventDisableTiming);
    cudaEventCreateWithFlags(&ev_a0, cudaEventDisableTiming);
    cudaEventCreateWithFlags(&ev_a1, cudaEventDisableTiming);
    cudaEventCreateWithFlags(&ev_r, cudaEventDisableTiming);

    // ---- prep fork: w1/w2 transposes (s2)  ||  hs split (main) ----
    cudaEventRecord(ev0, 0);
    cudaStreamWaitEvent(s2, ev0, 0);
    transpose_split_kernel<0><<<dim3(96, 32), dim3(32, 8), 0, s2>>>(w1, 3 * EMB);
    cudaEventRecord(ev1, s2);                       // qkv gate: w1t ready
    transpose_split_kernel<1><<<dim3(32, 32), dim3(32, 8), 0, s2>>>(w2, EMB);
    cudaEventRecord(evw2, s2);                      // proj gate: w2t ready

    split_kernel<<<(NTOK * EMB / 4) / 256, 256>>>(hs);
    cudaStreamWaitEvent(0, ev1, 0);

    // ---- pipelined main chain ----
    // qkv half 1 (tokens 0..2047 = batch 0)
    mma_gemm<0><<<dim3(24, 16), 128, GEMM_SMEM>>>(b1, nullptr, 0);
    cudaEventRecord(ev_q1, 0);
    // qkv half 2 (batch 1) on main, concurrent with attn_b0 on s2
    mma_gemm<0><<<dim3(24, 16), 128, GEMM_SMEM>>>(b1, nullptr, 2048);

    cudaStreamWaitEvent(s2, ev_q1, 0);
    attn_kernel<<<dim3(32, 16), 128, ATTN_SMEM, s2>>>(wts, 0);    // batch 0
    cudaEventRecord(ev_a0, s2);
    rescale_kernel<<<NH * S_LEN, 128, 0, s2>>>(wts, 0);           // bh 0..15

    // attn batch 1 on main (after qkv_h2), concurrent with rescale_b0
    attn_kernel<<<dim3(32, 16), 128, ATTN_SMEM>>>(wts, 16);
    cudaEventRecord(ev_a1, 0);

    // rescale batch 1 on s2, concurrent with proj
    cudaStreamWaitEvent(s2, ev_a1, 0);
    rescale_kernel<<<NH * S_LEN, 128, 0, s2>>>(wts, NH * S_LEN);
    cudaEventRecord(ev_r, s2);

    // proj on main: needs g_ao from both attn halves + w2t
    cudaStreamWaitEvent(0, ev_a0, 0);
    cudaStreamWaitEvent(0, evw2, 0);
    mma_gemm<1><<<dim3(8, 32), 128, GEMM_SMEM>>>(b2, attn_out, 0);
    cudaStreamWaitEvent(0, ev_r, 0);                 // join
}

// round 16
// speedup vs baseline: 1.1461x; 1.0090x over previous
#include <cuda_runtime.h>
#include <cuda_bf16.h>
#include <float.h>
#include <math.h>
#include <stdint.h>

#define S_LEN 2048
#define EMB   1024
#define NH    16
#define HD    64
#define NB    2
#define NTOK  (NB * S_LEN)   // 4096

// ---------------- scratch (device globals: no allocation allowed) ------------
__device__ float g_linv[(size_t)NB * NH * S_LEN];     // per-row 1/l

__device__ __nv_bfloat16 g_qh[(size_t)NB * NH * S_LEN * HD];  // [B,H,S,D]
__device__ __nv_bfloat16 g_ql[(size_t)NB * NH * S_LEN * HD];
__device__ __nv_bfloat16 g_kh[(size_t)NB * NH * S_LEN * HD];
__device__ __nv_bfloat16 g_kl[(size_t)NB * NH * S_LEN * HD];
__device__ __nv_bfloat16 g_vh[(size_t)NB * NH * S_LEN * HD];
__device__ __nv_bfloat16 g_vl[(size_t)NB * NH * S_LEN * HD];
__device__ __nv_bfloat16 g_hs_hi[(size_t)NTOK * EMB];
__device__ __nv_bfloat16 g_hs_lo[(size_t)NTOK * EMB];
__device__ __nv_bfloat16 g_ao_hi[(size_t)NTOK * EMB];
__device__ __nv_bfloat16 g_ao_lo[(size_t)NTOK * EMB];
__device__ __nv_bfloat16 g_w1t_hi[(size_t)3 * EMB * EMB];  // [N=3072, K=1024]
__device__ __nv_bfloat16 g_w1t_lo[(size_t)3 * EMB * EMB];
__device__ __nv_bfloat16 g_w2t_hi[(size_t)EMB * EMB];      // [N=1024, K=1024]
__device__ __nv_bfloat16 g_w2t_lo[(size_t)EMB * EMB];

// ---------------- warp-MMA helpers ------------------------------------------
__device__ __forceinline__ uint32_t smem_u32(const void* p) {
    uint32_t a;
    asm("{ .reg .u64 t; cvta.to.shared.u64 t, %1; cvt.u32.u64 %0, t; }"
        : "=r"(a) : "l"(p));
    return a;
}
__device__ __forceinline__ void ldsm4(uint32_t& r0, uint32_t& r1,
                                      uint32_t& r2, uint32_t& r3, uint32_t addr) {
    asm volatile("ldmatrix.sync.aligned.m8n8.x4.shared.b16 {%0,%1,%2,%3}, [%4];"
                 : "=r"(r0), "=r"(r1), "=r"(r2), "=r"(r3) : "r"(addr));
}
__device__ __forceinline__ void ldsm4t(uint32_t& r0, uint32_t& r1,
                                       uint32_t& r2, uint32_t& r3, uint32_t addr) {
    asm volatile("ldmatrix.sync.aligned.m8n8.x4.trans.shared.b16 {%0,%1,%2,%3}, [%4];"
                 : "=r"(r0), "=r"(r1), "=r"(r2), "=r"(r3) : "r"(addr));
}
__device__ __forceinline__ void mma16816(float* c, const uint32_t* a,
                                         uint32_t b0, uint32_t b1) {
    asm volatile(
        "mma.sync.aligned.m16n8k16.row.col.f32.bf16.bf16.f32 "
        "{%0,%1,%2,%3}, {%4,%5,%6,%7}, {%8,%9}, {%0,%1,%2,%3};"
        : "+f"(c[0]), "+f"(c[1]), "+f"(c[2]), "+f"(c[3])
        : "r"(a[0]), "r"(a[1]), "r"(a[2]), "r"(a[3]), "r"(b0), "r"(b1));
}
__device__ __forceinline__ void cp16(uint32_t dst, const void* src) {
    asm volatile("cp.async.cg.shared.global [%0], [%1], 16;"
                 :: "r"(dst), "l"(src) : "memory");
}
#define CP_COMMIT() asm volatile("cp.async.commit_group;" ::: "memory")
template<int N>
__device__ __forceinline__ void cp_wait() {
    asm volatile("cp.async.wait_group %0;" :: "n"(N) : "memory");
}

// =============================================================================
// split-bf16 HMMA GEMM (round-10 loop), with m-base offset for half launches.
// =============================================================================
#define SP 40   // smem row pitch (bf16)
#define GEMM_SMEM (2 * 4 * 128 * SP * 2)   // 81920 B

template<int MODE>
__global__ __launch_bounds__(128, 2)
void mma_gemm(const float* __restrict__ bias, float* __restrict__ Cout,
              int mbase) {
    extern __shared__ __nv_bfloat16 smg[];

    const int tid = threadIdx.x;
    const int wid = tid >> 5, lane = tid & 31;
    const int K = EMB;
    const int m0 = mbase + blockIdx.y * 128;
    const int n0 = blockIdx.x * 128;
    const int wm = wid & 1;
    const int wnw = wid >> 1;

    const __nv_bfloat16* __restrict__ gsrc[4] = {
        MODE ? g_ao_hi : g_hs_hi, MODE ? g_ao_lo : g_hs_lo,
        MODE ? g_w2t_hi : g_w1t_hi, MODE ? g_w2t_lo : g_w1t_lo};
    const int rb[4] = {m0, m0, n0, n0};

    const uint32_t sb = smem_u32(smg);
    const int BUF = 4 * 128 * SP;

    float acc[4][8][4];
#pragma unroll
    for (int i = 0; i < 4; i++)
#pragma unroll
        for (int j = 0; j < 8; j++)
#pragma unroll
            for (int k = 0; k < 4; k++) acc[i][j][k] = 0.f;

    const int grp = lane >> 3, lr = lane & 7;
    const int a_row = ((grp & 1) << 3) + lr;
    const int a_colh = (grp >> 1) << 3;
    const int b_row = ((grp >> 1) << 3) + lr;
    const int b_colh = (grp & 1) << 3;

    auto issue = [&](int t, int buf) {
#pragma unroll
        for (int arr = 0; arr < 4; arr++) {
#pragma unroll
            for (int r = 0; r < 4; r++) {
                int idx = r * 128 + tid;
                int row = idx >> 2, seg = idx & 3;
                cp16(sb + (buf * BUF + arr * 128 * SP + row * SP + seg * 8) * 2,
                     gsrc[arr] + (size_t)(rb[arr] + row) * K + t * 32 + seg * 8);
            }
        }
        CP_COMMIT();
    };

    issue(0, 0);

    const int nt = K / 32;
    for (int t = 0; t < nt; t++) {
        const int buf = t & 1;
        if (t + 1 < nt) { issue(t + 1, buf ^ 1); cp_wait<1>(); }
        else cp_wait<0>();
        __syncthreads();

        const uint32_t base = sb + buf * BUF * 2;
        const uint32_t aofs_hi = base;
        const uint32_t aofs_lo = base + 128 * SP * 2;
        const uint32_t bofs_hi = base + 2 * 128 * SP * 2;
        const uint32_t bofs_lo = base + 3 * 128 * SP * 2;

#pragma unroll
        for (int ks = 0; ks < 2; ks++) {
            const int k0 = ks * 16;
            uint32_t ah[4][4], al[4][4];
#pragma unroll
            for (int ma = 0; ma < 4; ma++) {
                int row = wm * 64 + ma * 16 + a_row;
                ldsm4(ah[ma][0], ah[ma][1], ah[ma][2], ah[ma][3],
                      aofs_hi + (row * SP + k0 + a_colh) * 2);
                ldsm4(al[ma][0], al[ma][1], al[ma][2], al[ma][3],
                      aofs_lo + (row * SP + k0 + a_colh) * 2);
            }
#pragma unroll
            for (int nb = 0; nb < 4; nb++) {
                int row = wnw * 64 + nb * 16 + b_row;
                int col = k0 + b_colh;
                uint32_t bh0, bh1, bh2, bh3, bl0, bl1, bl2, bl3;
                ldsm4(bh0, bh1, bh2, bh3, bofs_hi + (row * SP + col) * 2);
                ldsm4(bl0, bl1, bl2, bl3, bofs_lo + (row * SP + col) * 2);
#pragma unroll
                for (int ma = 0; ma < 4; ma++) {
                    mma16816(acc[ma][nb * 2 + 0], ah[ma], bh0, bh1);
                    mma16816(acc[ma][nb * 2 + 0], ah[ma], bl0, bl1);
                    mma16816(acc[ma][nb * 2 + 0], al[ma], bh0, bh1);
                    mma16816(acc[ma][nb * 2 + 1], ah[ma], bh2, bh3);
                    mma16816(acc[ma][nb * 2 + 1], ah[ma], bl2, bl3);
                    mma16816(acc[ma][nb * 2 + 1], al[ma], bh2, bh3);
                }
            }
        }
        __syncthreads();
    }

    // epilogue
#pragma unroll
    for (int ma = 0; ma < 4; ma++) {
#pragma unroll
        for (int na = 0; na < 8; na++) {
            float* c = acc[ma][na];
            const int gn = n0 + wnw * 64 + na * 8 + ((lane & 3) << 1);
            const float bx = bias[gn], by = bias[gn + 1];
            const int gr0 = m0 + wm * 64 + ma * 16 + (lane >> 2);
            if (MODE == 0) {
                const int which = gn >> 10;
                const int head  = (gn & 1023) >> 6;
                const int d     = gn & 63;
                __nv_bfloat16* dh = (which == 0) ? g_qh : ((which == 1) ? g_kh : g_vh);
                __nv_bfloat16* dl = (which == 0) ? g_ql : ((which == 1) ? g_kl : g_vl);
#pragma unroll
                for (int rr = 0; rr < 2; rr++) {
                    int gr = gr0 + rr * 8;
                    float x = c[rr * 2 + 0] + bx, y = c[rr * 2 + 1] + by;
                    __nv_bfloat162 h2 = __float22bfloat162_rn(make_float2(x, y));
                    __nv_bfloat162 l2 = __float22bfloat162_rn(
                        make_float2(x - __bfloat162float(h2.x),
                                    y - __bfloat162float(h2.y)));
                    size_t o = (((size_t)(gr >> 11) * NH + head) * S_LEN
                                + (gr & 2047)) * HD + d;
                    *(__nv_bfloat162*)&dh[o] = h2;
                    *(__nv_bfloat162*)&dl[o] = l2;
                }
            } else {
#pragma unroll
                for (int rr = 0; rr < 2; rr++) {
                    int gr = gr0 + rr * 8;
                    float2 o = {c[rr * 2 + 0] + bx, c[rr * 2 + 1] + by};
                    *(float2*)&Cout[(size_t)gr * EMB + gn] = o;
                }
            }
        }
    }
}

// =============================================================================
// HMMA causal attention with cp.async K/V prefetch + bh-base offset.
// =============================================================================
#define AP 72
#define T64 (64 * AP)
#define ATTN_SMEM (8 * T64 * 2)              // 73728 B

__global__ __launch_bounds__(128, 3)
void attn_kernel(float* __restrict__ wout, int bhbase) {
    extern __shared__ __nv_bfloat16 sma[];
    __nv_bfloat16* const Qh = sma;
    __nv_bfloat16* const Ql = sma + T64;

    const int tid = threadIdx.x;
    const int lane = tid & 31, wid = tid >> 5;
    const int wm = wid & 1, wn = wid >> 1;
    const int qt = blockIdx.x;
    const int bh = bhbase + blockIdx.y;
    const int q0 = qt * 64;
    const int b = bh >> 4, h = bh & 15;
    const float scale = 0.125f;

    const size_t hb = (size_t)bh * S_LEN * HD;
    const uint32_t sb = smem_u32(sma);
    const uint32_t uQh = sb, uQl = sb + T64 * 2;
    const uint32_t uKh = sb + 2 * T64 * 2, uKl = sb + 3 * T64 * 2;
    const uint32_t uVh = sb + 4 * T64 * 2, uVl = sb + 5 * T64 * 2;
    const uint32_t uPh = sb + 6 * T64 * 2, uPl = sb + 7 * T64 * 2;
    __nv_bfloat16* const Ph = sma + 6 * T64;
    __nv_bfloat16* const Pl = sma + 7 * T64;

    // Q tile (one-time, direct loads)
#pragma unroll
    for (int i = 0; i < 4; i++) {
        int idx = i * 128 + tid;
        int row = idx >> 3, seg = idx & 7;
        size_t go = hb + (size_t)(q0 + row) * HD + seg * 8;
        *(uint4*)&Qh[row * AP + seg * 8] = *(const uint4*)&g_qh[go];
        *(uint4*)&Ql[row * AP + seg * 8] = *(const uint4*)&g_ql[go];
    }

    auto issue_K = [&](int kt) {
#pragma unroll
        for (int i = 0; i < 4; i++) {
            int idx = i * 128 + tid;
            int row = idx >> 3, seg = idx & 7;
            size_t go = hb + (size_t)(kt * 64 + row) * HD + seg * 8;
            cp16(uKh + (row * AP + seg * 8) * 2, &g_kh[go]);
            cp16(uKl + (row * AP + seg * 8) * 2, &g_kl[go]);
        }
        CP_COMMIT();
    };
    auto issue_V = [&](int kt) {
#pragma unroll
        for (int i = 0; i < 4; i++) {
            int idx = i * 128 + tid;
            int row = idx >> 3, seg = idx & 7;
            size_t go = hb + (size_t)(kt * 64 + row) * HD + seg * 8;
            cp16(uVh + (row * AP + seg * 8) * 2, &g_vh[go]);
            cp16(uVl + (row * AP + seg * 8) * 2, &g_vl[go]);
        }
        CP_COMMIT();
    };

    const int grp = lane >> 3, lr = lane & 7;
    const int a_row = ((grp & 1) << 3) + lr;
    const int a_colh = (grp >> 1) << 3;
    const int b_row = ((grp >> 1) << 3) + lr;
    const int b_colh = (grp & 1) << 3;

    float oacc[2][4][4];
#pragma unroll
    for (int i = 0; i < 2; i++)
#pragma unroll
        for (int j = 0; j < 4; j++)
#pragma unroll
            for (int k = 0; k < 4; k++) oacc[i][j][k] = 0.f;
    float lacc[2][2] = {{0.f, 0.f}, {0.f, 0.f}};

    issue_K(0);

    for (int kt = 0; kt <= qt; kt++) {
        __syncthreads();            // prev PV done: V, P buffers free (Q on kt=0)
        issue_V(kt);                // lands during QK phase
        cp_wait<1>();               // K(kt) complete
        __syncthreads();

        // ---------- S = Q K^T ----------
        float sacc[2][4][4];
#pragma unroll
        for (int i = 0; i < 2; i++)
#pragma unroll
            for (int j = 0; j < 4; j++)
#pragma unroll
                for (int k = 0; k < 4; k++) sacc[i][j][k] = 0.f;

#pragma unroll
        for (int kc = 0; kc < 4; kc++) {
            const int k0 = kc * 16;
            uint32_t ah[2][4], al[2][4];
#pragma unroll
            for (int ma = 0; ma < 2; ma++) {
                int row = wm * 32 + ma * 16 + a_row;
                ldsm4(ah[ma][0], ah[ma][1], ah[ma][2], ah[ma][3],
                      uQh + (row * AP + k0 + a_colh) * 2);
                ldsm4(al[ma][0], al[ma][1], al[ma][2], al[ma][3],
                      uQl + (row * AP + k0 + a_colh) * 2);
            }
#pragma unroll
            for (int nb = 0; nb < 2; nb++) {
                int row = wn * 32 + nb * 16 + b_row;
                uint32_t bh0, bh1, bh2, bh3, bl0, bl1, bl2, bl3;
                ldsm4(bh0, bh1, bh2, bh3, uKh + (row * AP + k0 + b_colh) * 2);
                ldsm4(bl0, bl1, bl2, bl3, uKl + (row * AP + k0 + b_colh) * 2);
#pragma unroll
                for (int ma = 0; ma < 2; ma++) {
                    mma16816(sacc[ma][nb * 2 + 0], ah[ma], bh0, bh1);
                    mma16816(sacc[ma][nb * 2 + 0], ah[ma], bl0, bl1);
                    mma16816(sacc[ma][nb * 2 + 0], al[ma], bh0, bh1);
                    mma16816(sacc[ma][nb * 2 + 1], ah[ma], bh2, bh3);
                    mma16816(sacc[ma][nb * 2 + 1], ah[ma], bl2, bl3);
                    mma16816(sacc[ma][nb * 2 + 1], al[ma], bh2, bh3);
                }
            }
        }

        // ---------- exp, raw weights out, P -> smem hi/lo ----------
        const bool diag = (kt == qt);
#pragma unroll
        for (int ma = 0; ma < 2; ma++) {
#pragma unroll
            for (int na = 0; na < 4; na++) {
                float* c = sacc[ma][na];
                const int rl0 = wm * 32 + ma * 16 + (lane >> 2);
                const int cl = wn * 32 + na * 8 + ((lane & 3) << 1);
                const int gr0 = q0 + rl0, gc = kt * 64 + cl;
                float e00 = __expf(c[0] * scale);
                float e01 = __expf(c[1] * scale);
                float e10 = __expf(c[2] * scale);
                float e11 = __expf(c[3] * scale);
                if (diag) {
                    if (gc > gr0)     e00 = 0.f;
                    if (gc + 1 > gr0) e01 = 0.f;
                    if (gc > gr0 + 8)     e10 = 0.f;
                    if (gc + 1 > gr0 + 8) e11 = 0.f;
                }
                lacc[ma][0] += e00 + e01;
                lacc[ma][1] += e10 + e11;
                *(float2*)&wout[((size_t)bh * S_LEN + gr0) * S_LEN + gc] =
                    make_float2(e00, e01);
                *(float2*)&wout[((size_t)bh * S_LEN + gr0 + 8) * S_LEN + gc] =
                    make_float2(e10, e11);
                __nv_bfloat162 h0 = __float22bfloat162_rn(make_float2(e00, e01));
                __nv_bfloat162 h1 = __float22bfloat162_rn(make_float2(e10, e11));
                __nv_bfloat162 l0 = __float22bfloat162_rn(
                    make_float2(e00 - __bfloat162float(h0.x),
                                e01 - __bfloat162float(h0.y)));
                __nv_bfloat162 l1 = __float22bfloat162_rn(
                    make_float2(e10 - __bfloat162float(h1.x),
                                e11 - __bfloat162float(h1.y)));
                *(__nv_bfloat162*)&Ph[rl0 * AP + cl] = h0;
                *(__nv_bfloat162*)&Ph[(rl0 + 8) * AP + cl] = h1;
                *(__nv_bfloat162*)&Pl[rl0 * AP + cl] = l0;
                *(__nv_bfloat162*)&Pl[(rl0 + 8) * AP + cl] = l1;
            }
        }
        __syncthreads();            // P visible; K fully consumed

        if (kt < qt) { issue_K(kt + 1); cp_wait<1>(); }
        else cp_wait<0>();
        __syncthreads();            // V visible

        // ---------- O += P V ----------
#pragma unroll
        for (int kc = 0; kc < 4; kc++) {
            const int k0 = kc * 16;
            uint32_t ph[2][4], pl[2][4];
#pragma unroll
            for (int ma = 0; ma < 2; ma++) {
                int row = wm * 32 + ma * 16 + a_row;
                ldsm4(ph[ma][0], ph[ma][1], ph[ma][2], ph[ma][3],
                      uPh + (row * AP + k0 + a_colh) * 2);
                ldsm4(pl[ma][0], pl[ma][1], pl[ma][2], pl[ma][3],
                      uPl + (row * AP + k0 + a_colh) * 2);
            }
#pragma unroll
            for (int ndl = 0; ndl < 2; ndl++) {
                int vrow = k0 + ((grp & 1) << 3) + lr;
                int vcol = wn * 32 + ndl * 16 + ((grp >> 1) << 3);
                uint32_t vh0, vh1, vh2, vh3, vl0, vl1, vl2, vl3;
                ldsm4t(vh0, vh1, vh2, vh3, uVh + (vrow * AP + vcol) * 2);
                ldsm4t(vl0, vl1, vl2, vl3, uVl + (vrow * AP + vcol) * 2);
#pragma unroll
                for (int ma = 0; ma < 2; ma++) {
                    mma16816(oacc[ma][ndl * 2 + 0], ph[ma], vh0, vh1);
                    mma16816(oacc[ma][ndl * 2 + 0], ph[ma], vl0, vl1);
                    mma16816(oacc[ma][ndl * 2 + 0], pl[ma], vh0, vh1);
                    mma16816(oacc[ma][ndl * 2 + 1], ph[ma], vh2, vh3);
                    mma16816(oacc[ma][ndl * 2 + 1], ph[ma], vl2, vl3);
                    mma16816(oacc[ma][ndl * 2 + 1], pl[ma], vh2, vh3);
                }
            }
        }
    }

    // zero-fill fully-masked upper region (d_out poisoned)
    {
        const int ce = (qt + 1) * 64;
        const int n4 = (S_LEN - ce) >> 2;
        const float4 z = {0.f, 0.f, 0.f, 0.f};
        for (int i = tid; i < 64 * n4; i += 128) {
            int r = i / n4, c = i - r * n4;
            *(float4*)&wout[((size_t)bh * S_LEN + q0 + r) * S_LEN + ce + c * 4] = z;
        }
    }

    // ---------- l reduction ----------
    __syncthreads();
    float* fs = (float*)sma;

#pragma unroll
    for (int ma = 0; ma < 2; ma++) {
#pragma unroll
        for (int half = 0; half < 2; half++) {
            float v = lacc[ma][half];
            v += __shfl_xor_sync(0xffffffffu, v, 1);
            v += __shfl_xor_sync(0xffffffffu, v, 2);
            if ((lane & 3) == 0)
                fs[wn * 64 + wm * 32 + ma * 16 + half * 8 + (lane >> 2)] = v;
        }
    }
    __syncthreads();
    if (tid < 64) {
        float inv = 1.f / (fs[tid] + fs[64 + tid]);
        fs[128 + tid] = inv;
        g_linv[(size_t)bh * S_LEN + q0 + tid] = inv;
    }
    __syncthreads();

    // ---------- normalized O -> g_ao hi/lo ----------
#pragma unroll
    for (int ma = 0; ma < 2; ma++)
#pragma unroll
        for (int nd = 0; nd < 4; nd++) {
            float* c = oacc[ma][nd];
            int rl0 = wm * 32 + ma * 16 + (lane >> 2);
            int d0 = wn * 32 + nd * 8 + ((lane & 3) << 1);
#pragma unroll
            for (int rr = 0; rr < 2; rr++) {
                int rl = rl0 + rr * 8;
                float inv = fs[128 + rl];
                float x = c[rr * 2 + 0] * inv, y = c[rr * 2 + 1] * inv;
                __nv_bfloat162 h2 = __float22bfloat162_rn(make_float2(x, y));
                __nv_bfloat162 l2 = __float22bfloat162_rn(
                    make_float2(x - __bfloat162float(h2.x),
                                y - __bfloat162float(h2.y)));
                size_t tok = (size_t)b * S_LEN + q0 + rl;
                *(__nv_bfloat162*)&g_ao_hi[tok * EMB + h * HD + d0] = h2;
                *(__nv_bfloat162*)&g_ao_lo[tok * EMB + h * HD + d0] = l2;
            }
        }
}

// =============================================================================
// fp32 hidden_states -> (hi, lo) bf16 split.
// =============================================================================
__global__ void split_kernel(const float* __restrict__ src) {
    const size_t i4 = (size_t)blockIdx.x * blockDim.x + threadIdx.x;
    float4 v = ((const float4*)src)[i4];
    float f[4] = {v.x, v.y, v.z, v.w};
    __nv_bfloat16 h[4], l[4];
#pragma unroll
    for (int j = 0; j < 4; j++) {
        h[j] = __float2bfloat16(f[j]);
        l[j] = __float2bfloat16(f[j] - __bfloat162float(h[j]));
    }
    *(uint2*)&g_hs_hi[i4 * 4] = *(uint2*)h;
    *(uint2*)&g_hs_lo[i4 * 4] = *(uint2*)l;
}

// =============================================================================
// W [K,N] fp32 -> Wt_{hi,lo} [N,K] bf16.
// =============================================================================
template<int WHICH>
__global__ void transpose_split_kernel(const float* __restrict__ W, int N) {
    __shared__ float t[32][33];
    __nv_bfloat16* hi = WHICH ? g_w2t_hi : g_w1t_hi;
    __nv_bfloat16* lo = WHICH ? g_w2t_lo : g_w1t_lo;
    const int K = EMB;
    const int nx = blockIdx.x * 32, ky = blockIdx.y * 32;
    const int tx = threadIdx.x, ty = threadIdx.y;
#pragma unroll
    for (int i = 0; i < 4; i++)
        t[ty + i * 8][tx] = W[(size_t)(ky + ty + i * 8) * N + nx + tx];
    __syncthreads();
#pragma unroll
    for (int i = 0; i < 4; i++) {
        float v = t[tx][ty + i * 8];
        __nv_bfloat16 hh = __float2bfloat16(v);
        __nv_bfloat16 ll = __float2bfloat16(v - __bfloat162float(hh));
        size_t o = (size_t)(nx + ty + i * 8) * K + ky + tx;
        hi[o] = hh;
        lo[o] = ll;
    }
}

// =============================================================================
__global__ void rescale_kernel(float* __restrict__ wout, int rowbase) {
    const int row = rowbase + blockIdx.x;
    const int s = row & (S_LEN - 1);
    const float inv = g_linv[row];
    float4* p = (float4*)(wout + (size_t)row * S_LEN);
    const int n4 = (s + 4) >> 2;           // overshoot hits zeros (attn ran first)
    for (int i = threadIdx.x; i < n4; i += blockDim.x) {
        float4 v = p[i];
        v.x *= inv; v.y *= inv; v.z *= inv; v.w *= inv;
        p[i] = v;
    }
}

// =============================================================================
extern "C" void kernel_launch(void* const* d_in, const int* in_sizes, int n_in,
                              void* d_out, int out_size) {
    const float* hs = (const float*)d_in[0];
    const float* w1 = (const float*)d_in[1];
    const float* b1 = (const float*)d_in[2];
    const float* w2 = (const float*)d_in[3];
    const float* b2 = (const float*)d_in[4];

    float* out = (float*)d_out;
    float* attn_out = out;                           // [B,S,E]
    float* wts = out + (size_t)NTOK * EMB;           // [B,H,S,S]

    cudaFuncSetAttribute(mma_gemm<0>,
                         cudaFuncAttributeMaxDynamicSharedMemorySize, GEMM_SMEM);
    cudaFuncSetAttribute(mma_gemm<1>,
                         cudaFuncAttributeMaxDynamicSharedMemorySize, GEMM_SMEM);
    cudaFuncSetAttribute(attn_kernel,
                         cudaFuncAttributeMaxDynamicSharedMemorySize, ATTN_SMEM);

    // side stream + events for graph-captured fork/join
    cudaStream_t s2;
    cudaStreamCreateWithFlags(&s2, cudaStreamNonBlocking);
    cudaEvent_t ev0, ev1, evw2, ev_q1, ev_a0, ev_a1, ev_s2;
    cudaEventCreateWithFlags(&ev0, cudaEventDisableTiming);
    cudaEventCreateWithFlags(&ev1, cudaEventDisableTiming);
    cudaEventCreateWithFlags(&evw2, cudaEventDisableTiming);
    cudaEventCreateWithFlags(&ev_q1, cudaEventDisableTiming);
    cudaEventCreateWithFlags(&ev_a0, cudaEventDisableTiming);
    cudaEventCreateWithFlags(&ev_a1, cudaEventDisableTiming);
    cudaEventCreateWithFlags(&ev_s2, cudaEventDisableTiming);

    // ---- prep fork: w1/w2 transposes (s2)  ||  hs split (main) ----
    cudaEventRecord(ev0, 0);
    cudaStreamWaitEvent(s2, ev0, 0);
    transpose_split_kernel<0><<<dim3(96, 32), dim3(32, 8), 0, s2>>>(w1, 3 * EMB);
    cudaEventRecord(ev1, s2);                       // qkv gate: w1t ready
    transpose_split_kernel<1><<<dim3(32, 32), dim3(32, 8), 0, s2>>>(w2, EMB);
    cudaEventRecord(evw2, s2);                      // proj gate: w2t ready

    split_kernel<<<(NTOK * EMB / 4) / 256, 256>>>(hs);
    cudaStreamWaitEvent(0, ev1, 0);

    // ---- pipelined main chain ----
    // qkv half 1 (tokens 0..2047 = batch 0)
    mma_gemm<0><<<dim3(24, 16), 128, GEMM_SMEM>>>(b1, nullptr, 0);
    cudaEventRecord(ev_q1, 0);
    // qkv half 2 (batch 1) on main, concurrent with attn_b0 on s2
    mma_gemm<0><<<dim3(24, 16), 128, GEMM_SMEM>>>(b1, nullptr, 2048);

    cudaStreamWaitEvent(s2, ev_q1, 0);
    attn_kernel<<<dim3(32, 16), 128, ATTN_SMEM, s2>>>(wts, 0);    // batch 0
    cudaEventRecord(ev_a0, s2);

    // attn batch 1 on main (after qkv_h2)
    attn_kernel<<<dim3(32, 16), 128, ATTN_SMEM>>>(wts, 16);
    cudaEventRecord(ev_a1, 0);

    // s2 (after attn_b0): proj half 1 (needs w2t, evw2 already on s2 order)
    // + rescale batch 0 — both concurrent with attn_b1 on main
    mma_gemm<1><<<dim3(8, 16), 128, GEMM_SMEM, s2>>>(b2, attn_out, 0);
    rescale_kernel<<<NH * S_LEN, 128, 0, s2>>>(wts, 0);           // bh 0..15

    // rescale batch 1 on s2, concurrent with proj half 2 on main
    cudaStreamWaitEvent(s2, ev_a1, 0);
    rescale_kernel<<<NH * S_LEN, 128, 0, s2>>>(wts, NH * S_LEN);
    cudaEventRecord(ev_s2, s2);

    // proj half 2 on main: needs attn_b1's g_ao (program order) + w2t
    cudaStreamWaitEvent(0, evw2, 0);
    mma_gemm<1><<<dim3(8, 16), 128, GEMM_SMEM>>>(b2, attn_out, 2048);
    cudaStreamWaitEvent(0, ev_s2, 0);                // join
}